// round 9
// baseline (speedup 1.0000x reference)
#include <cuda_runtime.h>
#include <math.h>

#define NB 8
#define NL 4096
#define NH 8
#define NM 64
#define NCH 512

typedef unsigned long long u64x;

// ---------------- device scratch ----------------
__device__ ulonglong2 g_ts[4096];                  // (cc, ss) packed f32x2 of angle 2*pi*i/4096
__device__ float2 g_F[8 * NB * NM * NCH];          // [tq*2+tensor][b][mode-pos][ch]
__device__ float2 g_C[NB * NH * 64 * 64];          // [(h*8+b)][e][x] complex
__device__ float2 g_O[NB * NH * 64 * NM];          // [row][mode-pos]: (A, B) pre-scaled

// ---------------- f32x2 helpers ----------------
static __device__ __forceinline__ u64x fma2(u64x a, u64x b, u64x c) {
    u64x d; asm("fma.rn.f32x2 %0,%1,%2,%3;" : "=l"(d) : "l"(a), "l"(b), "l"(c)); return d;
}
static __device__ __forceinline__ u64x add2(u64x a, u64x b) {
    u64x d; asm("add.rn.f32x2 %0,%1,%2;" : "=l"(d) : "l"(a), "l"(b)); return d;
}
#define NEG1X2 0xBF800000BF800000ULL
#define KK2    0x3F3504F33F3504F3ULL   // (sqrt2/2, sqrt2/2)
#define NKK2   0xBF3504F3BF3504F3ULL   // negated
static __device__ __forceinline__ u64x sub2(u64x a, u64x b) { return fma2(b, NEG1X2, a); }
static __device__ __forceinline__ u64x neg2(u64x a) { return fma2(a, NEG1X2, 0ULL); }
static __device__ __forceinline__ void unpack2(u64x d, float& lo, float& hi) {
    asm("mov.b64 {%0,%1},%2;" : "=f"(lo), "=f"(hi) : "l"(d));
}

// ================= K0: trig table =================
__global__ void k0_init() {
    int i = blockIdx.x * 256 + threadIdx.x;
    if (i < 4096) {
        float s, c;
        sincospif((float)i / 2048.0f, &s, &c);
        u64x cc, ss;
        asm("mov.b64 %0,{%1,%1};" : "=l"(cc) : "f"(c));
        asm("mov.b64 %0,{%1,%1};" : "=l"(ss) : "f"(s));
        g_ts[i] = make_ulonglong2(cc, ss);
    }
}

// ================= K1: forward sparse DFT (radix-8, cp.async double-buffered) =================
// X[f] = sum_{t'} u_j(t') e^{-i 2pi f t'/4096}, j=f&7, u_j = sum_m x[t'+512m] w^{jm}, w=e^{-i pi/4}.
// accR=Re, accS accumulates -Im.  Chunk = [8 m][4 t'][128 ch].
template<int CLS>
static __device__ __forceinline__ void k1_chunk8(
    const ulonglong2* __restrict__ xs2, const ulonglong2* __restrict__ ts2,
    int lane, u64x accR[16], u64x accS[16], int idx[8], const int F[8])
{
#pragma unroll 2
    for (int tt = 0; tt < 4; tt++) {
        ulonglong2 X0 = xs2[(0 * 4 + tt) * 32 + lane];
        ulonglong2 X1 = xs2[(1 * 4 + tt) * 32 + lane];
        ulonglong2 X2 = xs2[(2 * 4 + tt) * 32 + lane];
        ulonglong2 X3 = xs2[(3 * 4 + tt) * 32 + lane];
        ulonglong2 X4 = xs2[(4 * 4 + tt) * 32 + lane];
        ulonglong2 X5 = xs2[(5 * 4 + tt) * 32 + lane];
        ulonglong2 X6 = xs2[(6 * 4 + tt) * 32 + lane];
        ulonglong2 X7 = xs2[(7 * 4 + tt) * 32 + lane];
        u64x Pr[2], Pi[2], nPi[2];
#pragma unroll
        for (int p = 0; p < 2; p++) {
            u64x a0 = p ? X0.y : X0.x;
            u64x a1 = p ? X1.y : X1.x;
            u64x a2 = p ? X2.y : X2.x;
            u64x a3 = p ? X3.y : X3.x;
            u64x a4 = p ? X4.y : X4.x;
            u64x a5 = p ? X5.y : X5.x;
            u64x a6 = p ? X6.y : X6.x;
            u64x a7 = p ? X7.y : X7.x;
            if (CLS == 0) {
                Pr[p] = add2(add2(add2(a0, a4), add2(a2, a6)), add2(add2(a1, a5), add2(a3, a7)));
            } else if (CLS == 4) {
                Pr[p] = sub2(add2(add2(a0, a4), add2(a2, a6)), add2(add2(a1, a5), add2(a3, a7)));
            } else if (CLS == 2 || CLS == 6) {
                u64x e0 = add2(a0, a4), e2 = add2(a2, a6);
                u64x e1 = add2(a1, a5), e3 = add2(a3, a7);
                Pr[p] = sub2(e0, e2);
                Pi[p] = (CLS == 2) ? sub2(e3, e1) : sub2(e1, e3);
                nPi[p] = neg2(Pi[p]);
            } else {
                u64x d04 = sub2(a0, a4), d62 = sub2(a6, a2);
                u64x s1 = sub2(a1, a5), s2 = sub2(a3, a7);
                u64x t1 = sub2(s1, s2), t2 = add2(s1, s2);
                if (CLS == 1) { Pr[p] = fma2(t1, KK2, d04);  Pi[p] = fma2(t2, NKK2, d62); }
                if (CLS == 3) { Pr[p] = fma2(t1, NKK2, d04); Pi[p] = neg2(fma2(t2, KK2, d62)); }
                if (CLS == 5) { Pr[p] = fma2(t1, NKK2, d04); Pi[p] = fma2(t2, KK2, d62); }
                if (CLS == 7) { Pr[p] = fma2(t1, KK2, d04);  Pi[p] = fma2(t2, KK2, neg2(d62)); }
                nPi[p] = neg2(Pi[p]);
            }
        }
#pragma unroll
        for (int k = 0; k < 8; k++) {
            ulonglong2 cs = ts2[idx[k]];
#pragma unroll
            for (int p = 0; p < 2; p++) {
                accR[k * 2 + p] = fma2(Pr[p], cs.x, accR[k * 2 + p]);
                accS[k * 2 + p] = fma2(Pr[p], cs.y, accS[k * 2 + p]);
                if (CLS != 0 && CLS != 4) {
                    accR[k * 2 + p] = fma2(Pi[p],  cs.y, accR[k * 2 + p]);
                    accS[k * 2 + p] = fma2(nPi[p], cs.x, accS[k * 2 + p]);
                }
            }
            idx[k] = (idx[k] + F[k]) & 4095;
        }
    }
}

// generic (mixed-class) fallback: direct per-row accumulation, no decimation
static __device__ __forceinline__ void k1_chunk_gen(
    const ulonglong2* __restrict__ xs2, const ulonglong2* __restrict__ ts2,
    int lane, u64x accR[16], u64x accS[16], int tp0, const int F[8])
{
    for (int tt = 0; tt < 4; tt++) {
#pragma unroll
        for (int m = 0; m < 8; m++) {
            ulonglong2 x = xs2[(m * 4 + tt) * 32 + lane];
            int tg = tp0 + tt + 512 * m;
#pragma unroll
            for (int k = 0; k < 8; k++) {
                int id = (F[k] * tg) & 4095;
                ulonglong2 cs = ts2[id];
                accR[k * 2 + 0] = fma2(x.x, cs.x, accR[k * 2 + 0]);
                accS[k * 2 + 0] = fma2(x.x, cs.y, accS[k * 2 + 0]);
                accR[k * 2 + 1] = fma2(x.y, cs.x, accR[k * 2 + 1]);
                accS[k * 2 + 1] = fma2(x.y, cs.y, accS[k * 2 + 1]);
            }
        }
    }
}

#define K1_SMEM (4096 * 16 + 2 * 4096 * 4 + 256)
__global__ void __launch_bounds__(256, 2) k1_forward(const float* __restrict__ qp,
                                                     const float* __restrict__ kp,
                                                     const int* __restrict__ iq,
                                                     const int* __restrict__ ikv) {
    extern __shared__ char sm[];
    ulonglong2* ts2 = (ulonglong2*)sm;
    float* xs = (float*)(ts2 + 4096);            // 2 buffers x [8 m][4 t'][128 ch]
    int* sMi = (int*)(xs + 2 * 4096);            // [64]

    const int ctile = blockIdx.x, b = blockIdx.y;
    const int tensor = blockIdx.z >> 2, tq = blockIdx.z & 3;
    const float* src = tensor ? kp : qp;
    const int* idxarr = tensor ? ikv : iq;
    const int tid = threadIdx.x, lane = tid & 31, warp = tid >> 5;

    for (int i = tid; i < 4096; i += 256) ts2[i] = g_ts[i];

    // bucket 64 modes by class (F&7); warp takes bucketed block per SMSP-balancing perm
    const int wperm_tab[8] = {0, 4, 2, 6, 1, 3, 5, 7};
    const int gw = wperm_tab[warp];
    const unsigned FULL = 0xffffffffu;
    int Flo = idxarr[lane], Fhi = idxarr[lane + 32];
    int clo = Flo & 7, chi = Fhi & 7;
    unsigned mlo[8], mhi[8];
    int off[9]; off[0] = 0;
#pragma unroll
    for (int c = 0; c < 8; c++) {
        mlo[c] = __ballot_sync(FULL, clo == c);
        mhi[c] = __ballot_sync(FULL, chi == c);
    }
#pragma unroll
    for (int c = 0; c < 8; c++) off[c + 1] = off[c] + __popc(mlo[c]) + __popc(mhi[c]);
    unsigned lm = (1u << lane) - 1u;
    int p_lo = off[clo] + __popc(mlo[clo] & lm);
    int p_hi = off[chi] + __popc(mlo[chi]) + __popc(mhi[chi] & lm);
    int F[8];
#pragma unroll
    for (int k = 0; k < 8; k++) {
        int tpos = gw * 8 + k;
        unsigned ba = __ballot_sync(FULL, p_lo == tpos);
        unsigned bb = __ballot_sync(FULL, p_hi == tpos);
        int m = ba ? (__ffs(ba) - 1) : (32 + __ffs(bb) - 1);
        if (lane == 0) sMi[tpos] = m;
        F[k] = __shfl_sync(FULL, (m < 32) ? Flo : Fhi, m & 31);
    }
    int jcls = F[0] & 7;
    bool uni = true;
#pragma unroll
    for (int k = 1; k < 8; k++) uni = uni && ((F[k] & 7) == jcls);

    u64x accR[16], accS[16]; int idx[8];
#pragma unroll
    for (int k = 0; k < 16; k++) { accR[k] = 0; accS[k] = 0; }

    const float* base = src + (size_t)b * NL * NCH + ctile * 128;
    unsigned xsu0 = (unsigned)__cvta_generic_to_shared(xs);

    // cp.async staging of one chunk (1024 float4) into buffer `buf`
#define K1_STAGE(buf, tp0v) do {                                                   \
        unsigned _bse = xsu0 + (buf) * 16384;                                      \
        _Pragma("unroll")                                                          \
        for (int ii = 0; ii < 4; ii++) {                                           \
            int i = ii * 256 + tid;                                                \
            int c4 = i & 31, tt = (i >> 5) & 3, mq = i >> 7;                       \
            const float* gp = base + (size_t)((tp0v) + tt + 512 * mq) * NCH + c4 * 4; \
            asm volatile("cp.async.cg.shared.global [%0], [%1], 16;"               \
                         :: "r"(_bse + i * 16), "l"(gp));                          \
        }                                                                          \
        asm volatile("cp.async.commit_group;");                                    \
    } while (0)

    K1_STAGE(0, tq * 128);

    for (int cc = 0; cc < 32; cc++) {
        const int tp0 = tq * 128 + cc * 4;
        if (cc < 31) {
            K1_STAGE((cc + 1) & 1, tp0 + 4);
            asm volatile("cp.async.wait_group 1;");
        } else {
            asm volatile("cp.async.wait_group 0;");
        }
        __syncthreads();
        const ulonglong2* xs2 = (const ulonglong2*)(xs + (cc & 1) * 4096);
#pragma unroll
        for (int k = 0; k < 8; k++) idx[k] = (F[k] * tp0) & 4095;
        if (uni) {
            switch (jcls) {
                case 0: k1_chunk8<0>(xs2, ts2, lane, accR, accS, idx, F); break;
                case 1: k1_chunk8<1>(xs2, ts2, lane, accR, accS, idx, F); break;
                case 2: k1_chunk8<2>(xs2, ts2, lane, accR, accS, idx, F); break;
                case 3: k1_chunk8<3>(xs2, ts2, lane, accR, accS, idx, F); break;
                case 4: k1_chunk8<4>(xs2, ts2, lane, accR, accS, idx, F); break;
                case 5: k1_chunk8<5>(xs2, ts2, lane, accR, accS, idx, F); break;
                case 6: k1_chunk8<6>(xs2, ts2, lane, accR, accS, idx, F); break;
                default: k1_chunk8<7>(xs2, ts2, lane, accR, accS, idx, F); break;
            }
        } else {
            k1_chunk_gen(xs2, ts2, lane, accR, accS, tp0, F);
        }
        __syncthreads();
    }
#undef K1_STAGE

    const int ch = ctile * 128 + lane * 4;
    float2* dst = g_F + ((size_t)((tq * 2 + tensor) * NB + b) * NM) * NCH;
#pragma unroll
    for (int k = 0; k < 8; k++) {
        float r0, r1, r2, r3, s0, s1, s2, s3;
        unpack2(accR[k * 2 + 0], r0, r1);
        unpack2(accS[k * 2 + 0], s0, s1);
        unpack2(accR[k * 2 + 1], r2, r3);
        unpack2(accS[k * 2 + 1], s2, s3);
        int mi = sMi[gw * 8 + k];
        float2* dp = &dst[(size_t)mi * NCH + ch];
        *(float4*)(dp)     = make_float4(r0, -s0, r1, -s1);
        *(float4*)(dp + 2) = make_float4(r2, -s2, r3, -s3);
    }
}

// ================= K2a: per-(b,h,xhalf) tanh attention, writes C =================
#define K2A_SMEM (32 * 64 * 8 + 64 * 65 * 8 + 64 * 33 * 8)
__global__ void __launch_bounds__(256, 3) k2a_attn() {
    extern __shared__ char sm[];
    float2* sFq  = (float2*)sm;              // [32 xl][64 e]
    float2* sFkT = sFq + 32 * 64;            // [64 e][65 y-pad]
    float2* sA   = sFkT + 64 * 65;           // [64 y][33 xl-pad]

    const int bh = blockIdx.x, b = bh >> 3, h = bh & 7;
    const int x0 = blockIdx.y * 32;
    const int tid = threadIdx.x;
    const size_t QSTR = (size_t)2 * NB * NM * NCH;

    for (int i = tid; i < 2048; i += 256) {
        int xl = i >> 6, e = i & 63;
        size_t o0 = ((size_t)(b) * NM + (x0 + xl)) * NCH + h * 64 + e;
        float2 a0 = g_F[o0], a1 = g_F[o0 + QSTR], a2 = g_F[o0 + 2 * QSTR], a3 = g_F[o0 + 3 * QSTR];
        sFq[xl * 64 + e] = make_float2(a0.x + a1.x + a2.x + a3.x, a0.y + a1.y + a2.y + a3.y);
    }
    for (int i = tid; i < 4096; i += 256) {
        int e = i & 63, f = i >> 6;
        size_t o0 = ((size_t)(NB + b) * NM + f) * NCH + h * 64 + e;
        float2 a0 = g_F[o0], a1 = g_F[o0 + QSTR], a2 = g_F[o0 + 2 * QSTR], a3 = g_F[o0 + 3 * QSTR];
        sFkT[e * 65 + f] = make_float2(a0.x + a1.x + a2.x + a3.x, a0.y + a1.y + a2.y + a3.y);
    }
    __syncthreads();

    // A[x][y] = tanh_c( sum_e Fq[e,x] * Fk[e,y] )
#pragma unroll 1
    for (int p = 0; p < 8; p++) {
        int i = p * 256 + tid, xl = i >> 6, y = i & 63;
        float re = 0.f, im = 0.f;
#pragma unroll 4
        for (int e = 0; e < 64; e++) {
            float2 a = sFq[xl * 64 + e];     // broadcast
            float2 c = sFkT[e * 65 + y];     // consecutive
            re += a.x * c.x - a.y * c.y;
            im += a.x * c.y + a.y * c.x;
        }
        sA[y * 33 + xl] = make_float2(tanhf(re), tanhf(im));
    }
    __syncthreads();

    // C[e][x] = sum_y A[x,y] * Fk[e,y] -> g_C
#pragma unroll 1
    for (int p = 0; p < 8; p++) {
        int i = p * 256 + tid, xl = i & 31, e = i >> 5;
        float re = 0.f, im = 0.f;
#pragma unroll 4
        for (int y = 0; y < 64; y++) {
            float2 a  = sA[y * 33 + xl];     // consecutive
            float2 kv = sFkT[e * 65 + y];    // broadcast
            re += a.x * kv.x - a.y * kv.y;
            im += a.x * kv.y + a.y * kv.x;
        }
        g_C[((size_t)(h * 8 + b) * 64 + e) * 64 + x0 + xl] = make_float2(re, im);
    }
}

// ================= K2b: weight contraction, w read exactly once =================
#define K2B_SMEM (8 * 64 * 4 * 8)
__global__ void __launch_bounds__(256, 4) k2b_wproj(const float* __restrict__ w1,
                                                    const float* __restrict__ w2,
                                                    const int* __restrict__ iq) {
    extern __shared__ char sm[];
    float2* sC = (float2*)sm;                // [8 b][64 e][4 xl]

    const int h = blockIdx.x, x0 = blockIdx.y * 4;
    const int tid = threadIdx.x;

    for (int i = tid; i < 2048; i += 256) {
        int xl = i & 3, e = (i >> 2) & 63, b = i >> 8;
        sC[(b * 64 + e) * 4 + xl] = g_C[((size_t)(h * 8 + b) * 64 + e) * 64 + x0 + xl];
    }
    __syncthreads();

    const int xl = tid & 3, x = x0 + xl, o = tid >> 2;
    float accR[8], accI[8];
#pragma unroll
    for (int b = 0; b < 8; b++) { accR[b] = 0.f; accI[b] = 0.f; }

    size_t wbase = (((size_t)h * 64) * 64 + o) * 64 + x;
#pragma unroll 4
    for (int e = 0; e < 64; e++) {
        float wr = w1[wbase + (size_t)e * 4096];
        float wi = w2[wbase + (size_t)e * 4096];
#pragma unroll
        for (int b = 0; b < 8; b++) {
            float2 c = sC[(b * 64 + e) * 4 + xl];
            accR[b] += c.x * wr - c.y * wi;
            accI[b] += c.x * wi + c.y * wr;
        }
    }

    int fx = iq[x];
    float s = ((fx == 0) || (fx == NL / 2) ? 1.0f : 2.0f) * 9.313225746154785e-10f; // 2^-30
#pragma unroll
    for (int b = 0; b < 8; b++) {
        int row = (b * 8 + h) * 64 + o;
        g_O[(size_t)row * NM + x] = make_float2(s * accR[b], -s * accI[b]);
    }
}

// ================= K3: inverse sparse DFT (radix-4, 128 rows/CTA, 4 rows/lane) =================
// S0 = (P0+P2)+O, S2 = (P0+P2)-O, S1 = (P0-P2)+R, S3 = (P0-P2)-R
// O = P1+P3, R = Q1-Q3;  P = A cc + B ss, Q = B cc - A ss
#define K3_SMEM (4096 * 16 + 32768 + 32768 + 128 * 65 * 4 + 64 * 8 + 64)
__global__ void __launch_bounds__(512, 1) k3_inverse(float* __restrict__ out,
                                                     const int* __restrict__ iq) {
    extern __shared__ char sm[];
    ulonglong2* ts2 = (ulonglong2*)sm;            // 64KB
    float* sA = (float*)(ts2 + 4096);             // [f][128 slots]
    float* sB = sA + 64 * 128;
    float* sT = sB + 64 * 128;                    // [128 rows][65]
    int2* sperm = (int2*)(sT + 128 * 65);
    int* soff = (int*)(sperm + 64);

    const int rt = blockIdx.x;                    // 32 row tiles of 128
    const int tq = blockIdx.y;                    // 4 t' quarters
    const int r0 = rt * 128;
    const int tid = threadIdx.x, lane = tid & 31, warp = tid >> 5;

    for (int i = tid; i < 4096; i += 512) ts2[i] = g_ts[i];
    // load g_O: slot layout so one LDS.128 per f gives rows (2l,2l+1,64+2l,64+2l+1)
    for (int i = tid; i < 8192; i += 512) {
        int rr = i >> 6, f = i & 63;
        float2 v = g_O[(size_t)(r0 + rr) * NM + f];
        int half = rr >> 6, pr = (rr & 63) >> 1, sl = half * 2 + (rr & 1);
        sA[f * 128 + pr * 4 + sl] = v.x;
        sB[f * 128 + pr * 4 + sl] = v.y;
    }
    if (warp == 0) {
        const unsigned FULL = 0xffffffffu;
        int Flo = iq[lane], Fhi = iq[lane + 32];
        int clo = Flo & 3, chi = Fhi & 3;
        unsigned mlo[4], mhi[4];
        int off[5]; off[0] = 0;
#pragma unroll
        for (int c = 0; c < 4; c++) {
            mlo[c] = __ballot_sync(FULL, clo == c);
            mhi[c] = __ballot_sync(FULL, chi == c);
        }
#pragma unroll
        for (int c = 0; c < 4; c++) off[c + 1] = off[c] + __popc(mlo[c]) + __popc(mhi[c]);
        unsigned lmm = (1u << lane) - 1u;
        int p_lo = off[clo] + __popc(mlo[clo] & lmm);
        int p_hi = off[chi] + __popc(mlo[chi]) + __popc(mhi[chi] & lmm);
        sperm[p_lo] = make_int2(lane, Flo);
        sperm[p_hi] = make_int2(lane + 32, Fhi);
        if (lane < 5) soff[lane] = off[lane];
    }
    __syncthreads();

    const ulonglong2* sAd = (const ulonglong2*)sA;   // 32 ulonglong2 per f
    const ulonglong2* sBd = (const ulonglong2*)sB;
    const int o0 = soff[0], o1 = soff[1], o2 = soff[2], o3 = soff[3], o4 = soff[4];

#pragma unroll 1
    for (int pass = 0; pass < 4; pass++) {
        const int t0 = tq * 256 + pass * 64 + warp * 4;
        u64x P0[8], P2[8], O[8], R[8];   // [j*2 + pack]
#pragma unroll
        for (int j = 0; j < 8; j++) { P0[j] = 0; P2[j] = 0; O[j] = 0; R[j] = 0; }

        // class 0 -> P0
#pragma unroll 2
        for (int pos = o0; pos < o1; pos++) {
            int2 pf = sperm[pos];
            ulonglong2 A = sAd[pf.x * 32 + lane], B = sBd[pf.x * 32 + lane];
            int id = (pf.y * t0) & 4095;
#pragma unroll
            for (int j = 0; j < 4; j++) {
                ulonglong2 cs = ts2[id];
                P0[j * 2 + 0] = fma2(A.x, cs.x, P0[j * 2 + 0]);  P0[j * 2 + 0] = fma2(B.x, cs.y, P0[j * 2 + 0]);
                P0[j * 2 + 1] = fma2(A.y, cs.x, P0[j * 2 + 1]);  P0[j * 2 + 1] = fma2(B.y, cs.y, P0[j * 2 + 1]);
                id = (id + pf.y) & 4095;
            }
        }
        // class 1 -> O += P, R += Q
#pragma unroll 2
        for (int pos = o1; pos < o2; pos++) {
            int2 pf = sperm[pos];
            ulonglong2 A = sAd[pf.x * 32 + lane], B = sBd[pf.x * 32 + lane];
            u64x nAx = neg2(A.x), nAy = neg2(A.y);
            int id = (pf.y * t0) & 4095;
#pragma unroll
            for (int j = 0; j < 4; j++) {
                ulonglong2 cs = ts2[id];
                O[j * 2 + 0] = fma2(A.x, cs.x, O[j * 2 + 0]);   O[j * 2 + 0] = fma2(B.x, cs.y, O[j * 2 + 0]);
                O[j * 2 + 1] = fma2(A.y, cs.x, O[j * 2 + 1]);   O[j * 2 + 1] = fma2(B.y, cs.y, O[j * 2 + 1]);
                R[j * 2 + 0] = fma2(B.x, cs.x, R[j * 2 + 0]);   R[j * 2 + 0] = fma2(nAx, cs.y, R[j * 2 + 0]);
                R[j * 2 + 1] = fma2(B.y, cs.x, R[j * 2 + 1]);   R[j * 2 + 1] = fma2(nAy, cs.y, R[j * 2 + 1]);
                id = (id + pf.y) & 4095;
            }
        }
        // class 2 -> P2
#pragma unroll 2
        for (int pos = o2; pos < o3; pos++) {
            int2 pf = sperm[pos];
            ulonglong2 A = sAd[pf.x * 32 + lane], B = sBd[pf.x * 32 + lane];
            int id = (pf.y * t0) & 4095;
#pragma unroll
            for (int j = 0; j < 4; j++) {
                ulonglong2 cs = ts2[id];
                P2[j * 2 + 0] = fma2(A.x, cs.x, P2[j * 2 + 0]);  P2[j * 2 + 0] = fma2(B.x, cs.y, P2[j * 2 + 0]);
                P2[j * 2 + 1] = fma2(A.y, cs.x, P2[j * 2 + 1]);  P2[j * 2 + 1] = fma2(B.y, cs.y, P2[j * 2 + 1]);
                id = (id + pf.y) & 4095;
            }
        }
        // class 3 -> O += P, R -= Q
#pragma unroll 2
        for (int pos = o3; pos < o4; pos++) {
            int2 pf = sperm[pos];
            ulonglong2 A = sAd[pf.x * 32 + lane], B = sBd[pf.x * 32 + lane];
            u64x nBx = neg2(B.x), nBy = neg2(B.y);
            int id = (pf.y * t0) & 4095;
#pragma unroll
            for (int j = 0; j < 4; j++) {
                ulonglong2 cs = ts2[id];
                O[j * 2 + 0] = fma2(A.x, cs.x, O[j * 2 + 0]);   O[j * 2 + 0] = fma2(B.x, cs.y, O[j * 2 + 0]);
                O[j * 2 + 1] = fma2(A.y, cs.x, O[j * 2 + 1]);   O[j * 2 + 1] = fma2(B.y, cs.y, O[j * 2 + 1]);
                R[j * 2 + 0] = fma2(nBx, cs.x, R[j * 2 + 0]);   R[j * 2 + 0] = fma2(A.x, cs.y, R[j * 2 + 0]);
                R[j * 2 + 1] = fma2(nBy, cs.x, R[j * 2 + 1]);   R[j * 2 + 1] = fma2(A.y, cs.y, R[j * 2 + 1]);
                id = (id + pf.y) & 4095;
            }
        }

        // reconstruct 4 quadrants, transpose through sT, store
#pragma unroll 1
        for (int m = 0; m < 4; m++) {
            __syncthreads();
#pragma unroll
            for (int j = 0; j < 4; j++) {
#pragma unroll
                for (int p = 0; p < 2; p++) {
                    u64x S;
                    u64x Ps = add2(P0[j * 2 + p], P2[j * 2 + p]);
                    u64x Pd = sub2(P0[j * 2 + p], P2[j * 2 + p]);
                    if (m == 0)      S = add2(Ps, O[j * 2 + p]);
                    else if (m == 1) S = add2(Pd, R[j * 2 + p]);
                    else if (m == 2) S = sub2(Ps, O[j * 2 + p]);
                    else             S = sub2(Pd, R[j * 2 + p]);
                    float v0, v1;
                    unpack2(S, v0, v1);
                    int tl = warp * 4 + j;
                    int rbase = p * 64 + 2 * lane;
                    sT[rbase * 65 + tl]       = v0;
                    sT[(rbase + 1) * 65 + tl] = v1;
                }
            }
            __syncthreads();
            int tbase = m * 1024 + tq * 256 + pass * 64;
#pragma unroll
            for (int ii = 0; ii < 4; ii++) {
                int i = ii * 512 + tid;        // 2048 float4
                int rr = i >> 4, c4 = i & 15;
                const float* sp = sT + rr * 65 + c4 * 4;
                float4 vv = make_float4(sp[0], sp[1], sp[2], sp[3]);
                *(float4*)&out[(size_t)(r0 + rr) * NL + tbase + c4 * 4] = vv;
            }
        }
    }
}

// ================= launch =================
extern "C" void kernel_launch(void* const* d_in, const int* in_sizes, int n_in,
                              void* d_out, int out_size) {
    const float* q  = (const float*)d_in[0];
    const float* k  = (const float*)d_in[1];
    // d_in[2] = v, never used by the reference
    const float* w1 = (const float*)d_in[3];
    const float* w2 = (const float*)d_in[4];
    const int* iq   = (const int*)d_in[5];
    const int* ikv  = (const int*)d_in[6];
    float* out = (float*)d_out;

    cudaFuncSetAttribute(k1_forward, cudaFuncAttributeMaxDynamicSharedMemorySize, K1_SMEM);
    cudaFuncSetAttribute(k2a_attn,   cudaFuncAttributeMaxDynamicSharedMemorySize, K2A_SMEM);
    cudaFuncSetAttribute(k2b_wproj,  cudaFuncAttributeMaxDynamicSharedMemorySize, K2B_SMEM);
    cudaFuncSetAttribute(k3_inverse, cudaFuncAttributeMaxDynamicSharedMemorySize, K3_SMEM);

    k0_init<<<16, 256>>>();
    k1_forward<<<dim3(4, NB, 8), 256, K1_SMEM>>>(q, k, iq, ikv);
    k2a_attn<<<dim3(NB * NH, 2), 256, K2A_SMEM>>>();
    k2b_wproj<<<dim3(NH, 16), 256, K2B_SMEM>>>(w1, w2, iq);
    k3_inverse<<<dim3(32, 4), 512, K3_SMEM>>>(out, iq);
}

// round 10
// speedup vs baseline: 1.1871x; 1.1871x over previous
#include <cuda_runtime.h>
#include <math.h>

#define NB 8
#define NL 4096
#define NH 8
#define NM 64
#define NCH 512

typedef unsigned long long u64x;

// ---------------- device scratch ----------------
__device__ ulonglong2 g_ts[4096];                  // (cc, ss) packed f32x2 of angle 2*pi*i/4096
__device__ float2 g_F[8 * NB * NM * NCH];          // [tq*2+tensor][b][mode-pos][ch]
__device__ float2 g_C[NB * NH * 64 * 64];          // [(h*8+b)][e][x] complex
__device__ float2 g_O[NB * NH * 64 * NM];          // [row][mode-pos]: (A, B) pre-scaled

// ---------------- f32x2 helpers ----------------
static __device__ __forceinline__ u64x fma2(u64x a, u64x b, u64x c) {
    u64x d; asm("fma.rn.f32x2 %0,%1,%2,%3;" : "=l"(d) : "l"(a), "l"(b), "l"(c)); return d;
}
static __device__ __forceinline__ u64x add2(u64x a, u64x b) {
    u64x d; asm("add.rn.f32x2 %0,%1,%2;" : "=l"(d) : "l"(a), "l"(b)); return d;
}
#define NEG1X2 0xBF800000BF800000ULL
#define KK2    0x3F3504F33F3504F3ULL   // (sqrt2/2, sqrt2/2)
#define NKK2   0xBF3504F3BF3504F3ULL   // negated
static __device__ __forceinline__ u64x sub2(u64x a, u64x b) { return fma2(b, NEG1X2, a); }
static __device__ __forceinline__ u64x neg2(u64x a) { return fma2(a, NEG1X2, 0ULL); }
static __device__ __forceinline__ void unpack2(u64x d, float& lo, float& hi) {
    asm("mov.b64 {%0,%1},%2;" : "=f"(lo), "=f"(hi) : "l"(d));
}

// ================= K0: trig table =================
__global__ void k0_init() {
    int i = blockIdx.x * 256 + threadIdx.x;
    if (i < 4096) {
        float s, c;
        sincospif((float)i / 2048.0f, &s, &c);
        u64x cc, ss;
        asm("mov.b64 %0,{%1,%1};" : "=l"(cc) : "f"(c));
        asm("mov.b64 %0,{%1,%1};" : "=l"(ss) : "f"(s));
        g_ts[i] = make_ulonglong2(cc, ss);
    }
}

// ================= K1: forward sparse DFT (radix-8, 8 modes/warp, 4 ch/lane) =================
// X[f] = sum_{t'} u_j(t') e^{-i 2pi f t'/4096}, j=f&7, u_j = sum_m x[t'+512m] w^{jm}, w=e^{-i pi/4}.
// accR=Re, accS accumulates -Im.  Loads are contiguous LDS.128 per lane (ulonglong2).
template<int CLS>
static __device__ __forceinline__ void k1_chunk8(
    const ulonglong2* __restrict__ xs2, const ulonglong2* __restrict__ ts2,
    int lane, u64x accR[16], u64x accS[16], int idx[8], const int F[8])
{
#pragma unroll 2
    for (int tt = 0; tt < 8; tt++) {
        ulonglong2 X0 = xs2[(0 * 8 + tt) * 32 + lane];
        ulonglong2 X1 = xs2[(1 * 8 + tt) * 32 + lane];
        ulonglong2 X2 = xs2[(2 * 8 + tt) * 32 + lane];
        ulonglong2 X3 = xs2[(3 * 8 + tt) * 32 + lane];
        ulonglong2 X4 = xs2[(4 * 8 + tt) * 32 + lane];
        ulonglong2 X5 = xs2[(5 * 8 + tt) * 32 + lane];
        ulonglong2 X6 = xs2[(6 * 8 + tt) * 32 + lane];
        ulonglong2 X7 = xs2[(7 * 8 + tt) * 32 + lane];
        u64x Pr[2], Pi[2], nPi[2];
#pragma unroll
        for (int p = 0; p < 2; p++) {
            u64x a0 = p ? X0.y : X0.x;
            u64x a1 = p ? X1.y : X1.x;
            u64x a2 = p ? X2.y : X2.x;
            u64x a3 = p ? X3.y : X3.x;
            u64x a4 = p ? X4.y : X4.x;
            u64x a5 = p ? X5.y : X5.x;
            u64x a6 = p ? X6.y : X6.x;
            u64x a7 = p ? X7.y : X7.x;
            if (CLS == 0) {
                Pr[p] = add2(add2(add2(a0, a4), add2(a2, a6)), add2(add2(a1, a5), add2(a3, a7)));
            } else if (CLS == 4) {
                Pr[p] = sub2(add2(add2(a0, a4), add2(a2, a6)), add2(add2(a1, a5), add2(a3, a7)));
            } else if (CLS == 2 || CLS == 6) {
                u64x e0 = add2(a0, a4), e2 = add2(a2, a6);
                u64x e1 = add2(a1, a5), e3 = add2(a3, a7);
                Pr[p] = sub2(e0, e2);
                Pi[p] = (CLS == 2) ? sub2(e3, e1) : sub2(e1, e3);
                nPi[p] = neg2(Pi[p]);
            } else {
                u64x d04 = sub2(a0, a4), d62 = sub2(a6, a2);
                u64x s1 = sub2(a1, a5), s2 = sub2(a3, a7);
                u64x t1 = sub2(s1, s2), t2 = add2(s1, s2);
                if (CLS == 1) { Pr[p] = fma2(t1, KK2, d04);  Pi[p] = fma2(t2, NKK2, d62); }
                if (CLS == 3) { Pr[p] = fma2(t1, NKK2, d04); Pi[p] = neg2(fma2(t2, KK2, d62)); }
                if (CLS == 5) { Pr[p] = fma2(t1, NKK2, d04); Pi[p] = fma2(t2, KK2, d62); }
                if (CLS == 7) { Pr[p] = fma2(t1, KK2, d04);  Pi[p] = fma2(t2, KK2, neg2(d62)); }
                nPi[p] = neg2(Pi[p]);
            }
        }
#pragma unroll
        for (int k = 0; k < 8; k++) {
            ulonglong2 cs = ts2[idx[k]];
#pragma unroll
            for (int p = 0; p < 2; p++) {
                accR[k * 2 + p] = fma2(Pr[p], cs.x, accR[k * 2 + p]);
                accS[k * 2 + p] = fma2(Pr[p], cs.y, accS[k * 2 + p]);
                if (CLS != 0 && CLS != 4) {
                    accR[k * 2 + p] = fma2(Pi[p],  cs.y, accR[k * 2 + p]);
                    accS[k * 2 + p] = fma2(nPi[p], cs.x, accS[k * 2 + p]);
                }
            }
            idx[k] = (idx[k] + F[k]) & 4095;
        }
    }
}

// generic (mixed-class) fallback: direct per-row accumulation, no decimation
static __device__ __forceinline__ void k1_chunk_gen(
    const ulonglong2* __restrict__ xs2, const ulonglong2* __restrict__ ts2,
    int lane, u64x accR[16], u64x accS[16], int tp0, const int F[8])
{
    for (int tt = 0; tt < 8; tt++) {
#pragma unroll
        for (int m = 0; m < 8; m++) {
            ulonglong2 x = xs2[(m * 8 + tt) * 32 + lane];
            int tg = tp0 + tt + 512 * m;
#pragma unroll
            for (int k = 0; k < 8; k++) {
                int id = (F[k] * tg) & 4095;
                ulonglong2 cs = ts2[id];
                accR[k * 2 + 0] = fma2(x.x, cs.x, accR[k * 2 + 0]);
                accS[k * 2 + 0] = fma2(x.x, cs.y, accS[k * 2 + 0]);
                accR[k * 2 + 1] = fma2(x.y, cs.x, accR[k * 2 + 1]);
                accS[k * 2 + 1] = fma2(x.y, cs.y, accS[k * 2 + 1]);
            }
        }
    }
}

#define K1_SMEM (4096 * 16 + 8 * 8 * 128 * 4 + 256)
__global__ void __launch_bounds__(256, 2) k1_forward(const float* __restrict__ qp,
                                                     const float* __restrict__ kp,
                                                     const int* __restrict__ iq,
                                                     const int* __restrict__ ikv) {
    extern __shared__ char sm[];
    ulonglong2* ts2 = (ulonglong2*)sm;
    float* xs = (float*)(ts2 + 4096);            // [8 m][8 t'][128 ch]
    int* sMi = (int*)(xs + 8 * 8 * 128);         // [64]
    const ulonglong2* xs2 = (const ulonglong2*)xs;

    const int ctile = blockIdx.x, b = blockIdx.y;
    const int tensor = blockIdx.z >> 2, tq = blockIdx.z & 3;
    const float* src = tensor ? kp : qp;
    const int* idxarr = tensor ? ikv : iq;
    const int tid = threadIdx.x, lane = tid & 31, warp = tid >> 5;

    for (int i = tid; i < 4096; i += 256) ts2[i] = g_ts[i];

    // bucket 64 modes by class (F&7); warp takes bucketed block per SMSP-balancing perm
    const int wperm_tab[8] = {0, 4, 2, 6, 1, 3, 5, 7};
    const int gw = wperm_tab[warp];
    const unsigned FULL = 0xffffffffu;
    int Flo = idxarr[lane], Fhi = idxarr[lane + 32];
    int clo = Flo & 7, chi = Fhi & 7;
    unsigned mlo[8], mhi[8];
    int off[9]; off[0] = 0;
#pragma unroll
    for (int c = 0; c < 8; c++) {
        mlo[c] = __ballot_sync(FULL, clo == c);
        mhi[c] = __ballot_sync(FULL, chi == c);
    }
#pragma unroll
    for (int c = 0; c < 8; c++) off[c + 1] = off[c] + __popc(mlo[c]) + __popc(mhi[c]);
    unsigned lm = (1u << lane) - 1u;
    int p_lo = off[clo] + __popc(mlo[clo] & lm);
    int p_hi = off[chi] + __popc(mlo[chi]) + __popc(mhi[chi] & lm);
    int F[8];
#pragma unroll
    for (int k = 0; k < 8; k++) {
        int tpos = gw * 8 + k;
        unsigned ba = __ballot_sync(FULL, p_lo == tpos);
        unsigned bb = __ballot_sync(FULL, p_hi == tpos);
        int m = ba ? (__ffs(ba) - 1) : (32 + __ffs(bb) - 1);
        if (lane == 0) sMi[tpos] = m;
        F[k] = __shfl_sync(FULL, (m < 32) ? Flo : Fhi, m & 31);
    }
    int jcls = F[0] & 7;
    bool uni = true;
#pragma unroll
    for (int k = 1; k < 8; k++) uni = uni && ((F[k] & 7) == jcls);

    u64x accR[16], accS[16]; int idx[8];
#pragma unroll
    for (int k = 0; k < 16; k++) { accR[k] = 0; accS[k] = 0; }

    const float* base = src + (size_t)b * NL * NCH + ctile * 128;

    for (int cc = 0; cc < 16; cc++) {
        const int tp0 = tq * 128 + cc * 8;
        __syncthreads();
#pragma unroll
        for (int ii = 0; ii < 8; ii++) {
            int i = ii * 256 + tid;                 // 2048 float4
            int c4 = i & 31, tt = (i >> 5) & 7, m = i >> 8;
            ((float4*)xs)[i] = *(const float4*)(base + (size_t)(tp0 + tt + 512 * m) * NCH + c4 * 4);
        }
        __syncthreads();
#pragma unroll
        for (int k = 0; k < 8; k++) idx[k] = (F[k] * tp0) & 4095;
        if (uni) {
            switch (jcls) {
                case 0: k1_chunk8<0>(xs2, ts2, lane, accR, accS, idx, F); break;
                case 1: k1_chunk8<1>(xs2, ts2, lane, accR, accS, idx, F); break;
                case 2: k1_chunk8<2>(xs2, ts2, lane, accR, accS, idx, F); break;
                case 3: k1_chunk8<3>(xs2, ts2, lane, accR, accS, idx, F); break;
                case 4: k1_chunk8<4>(xs2, ts2, lane, accR, accS, idx, F); break;
                case 5: k1_chunk8<5>(xs2, ts2, lane, accR, accS, idx, F); break;
                case 6: k1_chunk8<6>(xs2, ts2, lane, accR, accS, idx, F); break;
                default: k1_chunk8<7>(xs2, ts2, lane, accR, accS, idx, F); break;
            }
        } else {
            k1_chunk_gen(xs2, ts2, lane, accR, accS, tp0, F);
        }
    }

    const int ch = ctile * 128 + lane * 4;
    float2* dst = g_F + ((size_t)((tq * 2 + tensor) * NB + b) * NM) * NCH;
#pragma unroll
    for (int k = 0; k < 8; k++) {
        float r0, r1, r2, r3, s0, s1, s2, s3;
        unpack2(accR[k * 2 + 0], r0, r1);
        unpack2(accS[k * 2 + 0], s0, s1);
        unpack2(accR[k * 2 + 1], r2, r3);
        unpack2(accS[k * 2 + 1], s2, s3);
        int mi = sMi[gw * 8 + k];
        float2* dp = &dst[(size_t)mi * NCH + ch];
        *(float4*)(dp)     = make_float4(r0, -s0, r1, -s1);
        *(float4*)(dp + 2) = make_float4(r2, -s2, r3, -s3);
    }
}

// ================= K2a: per-(b,h,xhalf) tanh attention, writes C =================
#define K2A_SMEM (32 * 64 * 8 + 64 * 65 * 8 + 64 * 33 * 8)
__global__ void __launch_bounds__(256, 3) k2a_attn() {
    extern __shared__ char sm[];
    float2* sFq  = (float2*)sm;              // [32 xl][64 e]
    float2* sFkT = sFq + 32 * 64;            // [64 e][65 y-pad]
    float2* sA   = sFkT + 64 * 65;           // [64 y][33 xl-pad]

    const int bh = blockIdx.x, b = bh >> 3, h = bh & 7;
    const int x0 = blockIdx.y * 32;
    const int tid = threadIdx.x;
    const size_t QSTR = (size_t)2 * NB * NM * NCH;

    for (int i = tid; i < 2048; i += 256) {
        int xl = i >> 6, e = i & 63;
        size_t o0 = ((size_t)(b) * NM + (x0 + xl)) * NCH + h * 64 + e;
        float2 a0 = g_F[o0], a1 = g_F[o0 + QSTR], a2 = g_F[o0 + 2 * QSTR], a3 = g_F[o0 + 3 * QSTR];
        sFq[xl * 64 + e] = make_float2(a0.x + a1.x + a2.x + a3.x, a0.y + a1.y + a2.y + a3.y);
    }
    for (int i = tid; i < 4096; i += 256) {
        int e = i & 63, f = i >> 6;
        size_t o0 = ((size_t)(NB + b) * NM + f) * NCH + h * 64 + e;
        float2 a0 = g_F[o0], a1 = g_F[o0 + QSTR], a2 = g_F[o0 + 2 * QSTR], a3 = g_F[o0 + 3 * QSTR];
        sFkT[e * 65 + f] = make_float2(a0.x + a1.x + a2.x + a3.x, a0.y + a1.y + a2.y + a3.y);
    }
    __syncthreads();

    // A[x][y] = tanh_c( sum_e Fq[e,x] * Fk[e,y] )
#pragma unroll 1
    for (int p = 0; p < 8; p++) {
        int i = p * 256 + tid, xl = i >> 6, y = i & 63;
        float re = 0.f, im = 0.f;
#pragma unroll 4
        for (int e = 0; e < 64; e++) {
            float2 a = sFq[xl * 64 + e];     // broadcast
            float2 c = sFkT[e * 65 + y];     // consecutive
            re += a.x * c.x - a.y * c.y;
            im += a.x * c.y + a.y * c.x;
        }
        sA[y * 33 + xl] = make_float2(tanhf(re), tanhf(im));
    }
    __syncthreads();

    // C[e][x] = sum_y A[x,y] * Fk[e,y] -> g_C
#pragma unroll 1
    for (int p = 0; p < 8; p++) {
        int i = p * 256 + tid, xl = i & 31, e = i >> 5;
        float re = 0.f, im = 0.f;
#pragma unroll 4
        for (int y = 0; y < 64; y++) {
            float2 a  = sA[y * 33 + xl];     // consecutive
            float2 kv = sFkT[e * 65 + y];    // broadcast
            re += a.x * kv.x - a.y * kv.y;
            im += a.x * kv.y + a.y * kv.x;
        }
        g_C[((size_t)(h * 8 + b) * 64 + e) * 64 + x0 + xl] = make_float2(re, im);
    }
}

// ================= K2b: weight contraction, w read exactly once =================
#define K2B_SMEM (8 * 64 * 4 * 8)
__global__ void __launch_bounds__(256, 4) k2b_wproj(const float* __restrict__ w1,
                                                    const float* __restrict__ w2,
                                                    const int* __restrict__ iq) {
    extern __shared__ char sm[];
    float2* sC = (float2*)sm;                // [8 b][64 e][4 xl]

    const int h = blockIdx.x, x0 = blockIdx.y * 4;
    const int tid = threadIdx.x;

    for (int i = tid; i < 2048; i += 256) {
        int xl = i & 3, e = (i >> 2) & 63, b = i >> 8;
        sC[(b * 64 + e) * 4 + xl] = g_C[((size_t)(h * 8 + b) * 64 + e) * 64 + x0 + xl];
    }
    __syncthreads();

    const int xl = tid & 3, x = x0 + xl, o = tid >> 2;
    float accR[8], accI[8];
#pragma unroll
    for (int b = 0; b < 8; b++) { accR[b] = 0.f; accI[b] = 0.f; }

    size_t wbase = (((size_t)h * 64) * 64 + o) * 64 + x;
#pragma unroll 4
    for (int e = 0; e < 64; e++) {
        float wr = w1[wbase + (size_t)e * 4096];
        float wi = w2[wbase + (size_t)e * 4096];
#pragma unroll
        for (int b = 0; b < 8; b++) {
            float2 c = sC[(b * 64 + e) * 4 + xl];
            accR[b] += c.x * wr - c.y * wi;
            accI[b] += c.x * wi + c.y * wr;
        }
    }

    int fx = iq[x];
    float s = ((fx == 0) || (fx == NL / 2) ? 1.0f : 2.0f) * 9.313225746154785e-10f; // 2^-30
#pragma unroll
    for (int b = 0; b < 8; b++) {
        int row = (b * 8 + h) * 64 + o;
        g_O[(size_t)row * NM + x] = make_float2(s * accR[b], -s * accI[b]);
    }
}

// ================= K3: inverse sparse DFT (radix-4, 128 rows/CTA, 4 rows/lane) =================
// S0 = (P0+P2)+O, S2 = (P0+P2)-O, S1 = (P0-P2)+R, S3 = (P0-P2)-R
// O = P1+P3, R = Q1-Q3;  P = A cc + B ss, Q = B cc - A ss
#define K3_SMEM (4096 * 16 + 32768 + 32768 + 128 * 65 * 4 + 64 * 8 + 64)
__global__ void __launch_bounds__(512, 1) k3_inverse(float* __restrict__ out,
                                                     const int* __restrict__ iq) {
    extern __shared__ char sm[];
    ulonglong2* ts2 = (ulonglong2*)sm;            // 64KB
    float* sA = (float*)(ts2 + 4096);             // [f][128 slots]
    float* sB = sA + 64 * 128;
    float* sT = sB + 64 * 128;                    // [128 rows][65]
    int2* sperm = (int2*)(sT + 128 * 65);
    int* soff = (int*)(sperm + 64);

    const int rt = blockIdx.x;                    // 32 row tiles of 128
    const int tq = blockIdx.y;                    // 4 t' quarters
    const int r0 = rt * 128;
    const int tid = threadIdx.x, lane = tid & 31, warp = tid >> 5;

    for (int i = tid; i < 4096; i += 512) ts2[i] = g_ts[i];
    // load g_O: slot layout so one LDS.128 per f gives rows (2l,2l+1,64+2l,64+2l+1)
    for (int i = tid; i < 8192; i += 512) {
        int rr = i >> 6, f = i & 63;
        float2 v = g_O[(size_t)(r0 + rr) * NM + f];
        int half = rr >> 6, pr = (rr & 63) >> 1, sl = half * 2 + (rr & 1);
        sA[f * 128 + pr * 4 + sl] = v.x;
        sB[f * 128 + pr * 4 + sl] = v.y;
    }
    if (warp == 0) {
        const unsigned FULL = 0xffffffffu;
        int Flo = iq[lane], Fhi = iq[lane + 32];
        int clo = Flo & 3, chi = Fhi & 3;
        unsigned mlo[4], mhi[4];
        int off[5]; off[0] = 0;
#pragma unroll
        for (int c = 0; c < 4; c++) {
            mlo[c] = __ballot_sync(FULL, clo == c);
            mhi[c] = __ballot_sync(FULL, chi == c);
        }
#pragma unroll
        for (int c = 0; c < 4; c++) off[c + 1] = off[c] + __popc(mlo[c]) + __popc(mhi[c]);
        unsigned lmm = (1u << lane) - 1u;
        int p_lo = off[clo] + __popc(mlo[clo] & lmm);
        int p_hi = off[chi] + __popc(mlo[chi]) + __popc(mhi[chi] & lmm);
        sperm[p_lo] = make_int2(lane, Flo);
        sperm[p_hi] = make_int2(lane + 32, Fhi);
        if (lane < 5) soff[lane] = off[lane];
    }
    __syncthreads();

    const ulonglong2* sAd = (const ulonglong2*)sA;   // 32 ulonglong2 per f
    const ulonglong2* sBd = (const ulonglong2*)sB;
    const int o0 = soff[0], o1 = soff[1], o2 = soff[2], o3 = soff[3], o4 = soff[4];

#pragma unroll 1
    for (int pass = 0; pass < 4; pass++) {
        const int t0 = tq * 256 + pass * 64 + warp * 4;
        u64x P0[8], P2[8], O[8], R[8];   // [j*2 + pack]
#pragma unroll
        for (int j = 0; j < 8; j++) { P0[j] = 0; P2[j] = 0; O[j] = 0; R[j] = 0; }

        // class 0 -> P0
#pragma unroll 2
        for (int pos = o0; pos < o1; pos++) {
            int2 pf = sperm[pos];
            ulonglong2 A = sAd[pf.x * 32 + lane], B = sBd[pf.x * 32 + lane];
            int id = (pf.y * t0) & 4095;
#pragma unroll
            for (int j = 0; j < 4; j++) {
                ulonglong2 cs = ts2[id];
                P0[j * 2 + 0] = fma2(A.x, cs.x, P0[j * 2 + 0]);  P0[j * 2 + 0] = fma2(B.x, cs.y, P0[j * 2 + 0]);
                P0[j * 2 + 1] = fma2(A.y, cs.x, P0[j * 2 + 1]);  P0[j * 2 + 1] = fma2(B.y, cs.y, P0[j * 2 + 1]);
                id = (id + pf.y) & 4095;
            }
        }
        // class 1 -> O += P, R += Q
#pragma unroll 2
        for (int pos = o1; pos < o2; pos++) {
            int2 pf = sperm[pos];
            ulonglong2 A = sAd[pf.x * 32 + lane], B = sBd[pf.x * 32 + lane];
            u64x nAx = neg2(A.x), nAy = neg2(A.y);
            int id = (pf.y * t0) & 4095;
#pragma unroll
            for (int j = 0; j < 4; j++) {
                ulonglong2 cs = ts2[id];
                O[j * 2 + 0] = fma2(A.x, cs.x, O[j * 2 + 0]);   O[j * 2 + 0] = fma2(B.x, cs.y, O[j * 2 + 0]);
                O[j * 2 + 1] = fma2(A.y, cs.x, O[j * 2 + 1]);   O[j * 2 + 1] = fma2(B.y, cs.y, O[j * 2 + 1]);
                R[j * 2 + 0] = fma2(B.x, cs.x, R[j * 2 + 0]);   R[j * 2 + 0] = fma2(nAx, cs.y, R[j * 2 + 0]);
                R[j * 2 + 1] = fma2(B.y, cs.x, R[j * 2 + 1]);   R[j * 2 + 1] = fma2(nAy, cs.y, R[j * 2 + 1]);
                id = (id + pf.y) & 4095;
            }
        }
        // class 2 -> P2
#pragma unroll 2
        for (int pos = o2; pos < o3; pos++) {
            int2 pf = sperm[pos];
            ulonglong2 A = sAd[pf.x * 32 + lane], B = sBd[pf.x * 32 + lane];
            int id = (pf.y * t0) & 4095;
#pragma unroll
            for (int j = 0; j < 4; j++) {
                ulonglong2 cs = ts2[id];
                P2[j * 2 + 0] = fma2(A.x, cs.x, P2[j * 2 + 0]);  P2[j * 2 + 0] = fma2(B.x, cs.y, P2[j * 2 + 0]);
                P2[j * 2 + 1] = fma2(A.y, cs.x, P2[j * 2 + 1]);  P2[j * 2 + 1] = fma2(B.y, cs.y, P2[j * 2 + 1]);
                id = (id + pf.y) & 4095;
            }
        }
        // class 3 -> O += P, R -= Q
#pragma unroll 2
        for (int pos = o3; pos < o4; pos++) {
            int2 pf = sperm[pos];
            ulonglong2 A = sAd[pf.x * 32 + lane], B = sBd[pf.x * 32 + lane];
            u64x nBx = neg2(B.x), nBy = neg2(B.y);
            int id = (pf.y * t0) & 4095;
#pragma unroll
            for (int j = 0; j < 4; j++) {
                ulonglong2 cs = ts2[id];
                O[j * 2 + 0] = fma2(A.x, cs.x, O[j * 2 + 0]);   O[j * 2 + 0] = fma2(B.x, cs.y, O[j * 2 + 0]);
                O[j * 2 + 1] = fma2(A.y, cs.x, O[j * 2 + 1]);   O[j * 2 + 1] = fma2(B.y, cs.y, O[j * 2 + 1]);
                R[j * 2 + 0] = fma2(nBx, cs.x, R[j * 2 + 0]);   R[j * 2 + 0] = fma2(A.x, cs.y, R[j * 2 + 0]);
                R[j * 2 + 1] = fma2(nBy, cs.x, R[j * 2 + 1]);   R[j * 2 + 1] = fma2(A.y, cs.y, R[j * 2 + 1]);
                id = (id + pf.y) & 4095;
            }
        }

        // reconstruct 4 quadrants, transpose through sT, store
#pragma unroll 1
        for (int m = 0; m < 4; m++) {
            __syncthreads();
#pragma unroll
            for (int j = 0; j < 4; j++) {
#pragma unroll
                for (int p = 0; p < 2; p++) {
                    u64x S;
                    u64x Ps = add2(P0[j * 2 + p], P2[j * 2 + p]);
                    u64x Pd = sub2(P0[j * 2 + p], P2[j * 2 + p]);
                    if (m == 0)      S = add2(Ps, O[j * 2 + p]);
                    else if (m == 1) S = add2(Pd, R[j * 2 + p]);
                    else if (m == 2) S = sub2(Ps, O[j * 2 + p]);
                    else             S = sub2(Pd, R[j * 2 + p]);
                    float v0, v1;
                    unpack2(S, v0, v1);
                    int tl = warp * 4 + j;
                    int rbase = p * 64 + 2 * lane;
                    sT[rbase * 65 + tl]       = v0;
                    sT[(rbase + 1) * 65 + tl] = v1;
                }
            }
            __syncthreads();
            int tbase = m * 1024 + tq * 256 + pass * 64;
#pragma unroll
            for (int ii = 0; ii < 4; ii++) {
                int i = ii * 512 + tid;        // 2048 float4
                int rr = i >> 4, c4 = i & 15;
                const float* sp = sT + rr * 65 + c4 * 4;
                float4 vv = make_float4(sp[0], sp[1], sp[2], sp[3]);
                *(float4*)&out[(size_t)(r0 + rr) * NL + tbase + c4 * 4] = vv;
            }
        }
    }
}

// ================= launch =================
extern "C" void kernel_launch(void* const* d_in, const int* in_sizes, int n_in,
                              void* d_out, int out_size) {
    const float* q  = (const float*)d_in[0];
    const float* k  = (const float*)d_in[1];
    // d_in[2] = v, never used by the reference
    const float* w1 = (const float*)d_in[3];
    const float* w2 = (const float*)d_in[4];
    const int* iq   = (const int*)d_in[5];
    const int* ikv  = (const int*)d_in[6];
    float* out = (float*)d_out;

    cudaFuncSetAttribute(k1_forward, cudaFuncAttributeMaxDynamicSharedMemorySize, K1_SMEM);
    cudaFuncSetAttribute(k2a_attn,   cudaFuncAttributeMaxDynamicSharedMemorySize, K2A_SMEM);
    cudaFuncSetAttribute(k2b_wproj,  cudaFuncAttributeMaxDynamicSharedMemorySize, K2B_SMEM);
    cudaFuncSetAttribute(k3_inverse, cudaFuncAttributeMaxDynamicSharedMemorySize, K3_SMEM);

    k0_init<<<16, 256>>>();
    k1_forward<<<dim3(4, NB, 8), 256, K1_SMEM>>>(q, k, iq, ikv);
    k2a_attn<<<dim3(NB * NH, 2), 256, K2A_SMEM>>>();
    k2b_wproj<<<dim3(NH, 16), 256, K2B_SMEM>>>(w1, w2, iq);
    k3_inverse<<<dim3(32, 4), 512, K3_SMEM>>>(out, iq);
}

// round 11
// speedup vs baseline: 1.3396x; 1.1285x over previous
#include <cuda_runtime.h>
#include <math.h>

#define NB 8
#define NL 4096
#define NH 8
#define NM 64
#define NCH 512

typedef unsigned long long u64x;

// ---------------- device scratch ----------------
__device__ ulonglong2 g_ts[4096];                  // (cc, ss) packed f32x2 of angle 2*pi*i/4096
__device__ float2 g_F[8 * NB * NM * NCH];          // [tq*2+tensor][b][mode-pos][ch]
__device__ float2 g_C[NB * NH * 64 * 64];          // [(h*8+b)][e][x] complex
__device__ float2 g_O[NB * NH * 64 * NM];          // [row][mode-pos]: (A, B) pre-scaled

// ---------------- f32x2 helpers ----------------
static __device__ __forceinline__ u64x fma2(u64x a, u64x b, u64x c) {
    u64x d; asm("fma.rn.f32x2 %0,%1,%2,%3;" : "=l"(d) : "l"(a), "l"(b), "l"(c)); return d;
}
static __device__ __forceinline__ u64x add2(u64x a, u64x b) {
    u64x d; asm("add.rn.f32x2 %0,%1,%2;" : "=l"(d) : "l"(a), "l"(b)); return d;
}
#define NEG1X2 0xBF800000BF800000ULL
#define KK2    0x3F3504F33F3504F3ULL   // (sqrt2/2, sqrt2/2)
#define NKK2   0xBF3504F3BF3504F3ULL   // negated
static __device__ __forceinline__ u64x sub2(u64x a, u64x b) { return fma2(b, NEG1X2, a); }
static __device__ __forceinline__ u64x neg2(u64x a) { return fma2(a, NEG1X2, 0ULL); }
static __device__ __forceinline__ void unpack2(u64x d, float& lo, float& hi) {
    asm("mov.b64 {%0,%1},%2;" : "=f"(lo), "=f"(hi) : "l"(d));
}

// ================= K0: trig table =================
__global__ void k0_init() {
    int i = blockIdx.x * 256 + threadIdx.x;
    if (i < 4096) {
        float s, c;
        sincospif((float)i / 2048.0f, &s, &c);
        u64x cc, ss;
        asm("mov.b64 %0,{%1,%1};" : "=l"(cc) : "f"(c));
        asm("mov.b64 %0,{%1,%1};" : "=l"(ss) : "f"(s));
        g_ts[i] = make_ulonglong2(cc, ss);
    }
}

// ================= K1: forward sparse DFT (radix-8, shared butterfly in staging) =================
// X[f] = sum_{t'} u_j(t') e^{-i 2pi f t'/4096}, j=f&7, u_j = sum_m x[t'+512m] w^{jm}, w=e^{-i pi/4}.
// Staging computes per (t', ch): slots {P0,P4,P2r,P2i,d04,d62,t1,t2}; classes read only their slots:
//   u0 = P0 ; u4 = P4 ; u2 = P2r + i P2i ; u6 = P2r - i P2i
//   u1 = (d04 + k t1) + i(d62 - k t2) ; u3 = (d04 - k t1) - i(d62 + k t2)
//   u5 = (d04 - k t1) + i(d62 + k t2) ; u7 = (d04 + k t1) + i(k t2 - d62)    (k = sqrt2/2)
// accR=Re, accS accumulates -Im: accR += Pr*cc + Pi*ss ; accS += Pr*ss - Pi*cc.
template<int CLS>
static __device__ __forceinline__ void k1_chunk8(
    const ulonglong2* __restrict__ xs2, const ulonglong2* __restrict__ ts2,
    int lane, u64x accR[16], u64x accS[16], int idx[8], const int F[8])
{
#pragma unroll 2
    for (int tt = 0; tt < 8; tt++) {
        u64x Pr[2], Pi[2], nPi[2];
        if (CLS == 0) {
            ulonglong2 X = xs2[(0 * 8 + tt) * 32 + lane];
            Pr[0] = X.x; Pr[1] = X.y;
        } else if (CLS == 4) {
            ulonglong2 X = xs2[(1 * 8 + tt) * 32 + lane];
            Pr[0] = X.x; Pr[1] = X.y;
        } else if (CLS == 2) {
            ulonglong2 XR = xs2[(2 * 8 + tt) * 32 + lane];
            ulonglong2 XI = xs2[(3 * 8 + tt) * 32 + lane];
            Pr[0] = XR.x; Pr[1] = XR.y;
            Pi[0] = XI.x; Pi[1] = XI.y;
            nPi[0] = neg2(Pi[0]); nPi[1] = neg2(Pi[1]);
        } else if (CLS == 6) {
            ulonglong2 XR = xs2[(2 * 8 + tt) * 32 + lane];
            ulonglong2 XI = xs2[(3 * 8 + tt) * 32 + lane];
            Pr[0] = XR.x; Pr[1] = XR.y;
            nPi[0] = XI.x; nPi[1] = XI.y;
            Pi[0] = neg2(nPi[0]); Pi[1] = neg2(nPi[1]);
        } else {
            ulonglong2 D04 = xs2[(4 * 8 + tt) * 32 + lane];
            ulonglong2 D62 = xs2[(5 * 8 + tt) * 32 + lane];
            ulonglong2 T1  = xs2[(6 * 8 + tt) * 32 + lane];
            ulonglong2 T2  = xs2[(7 * 8 + tt) * 32 + lane];
#pragma unroll
            for (int p = 0; p < 2; p++) {
                u64x d04 = p ? D04.y : D04.x;
                u64x d62 = p ? D62.y : D62.x;
                u64x t1v = p ? T1.y : T1.x;
                u64x t2v = p ? T2.y : T2.x;
                if (CLS == 1) { Pr[p] = fma2(t1v, KK2, d04);  Pi[p] = fma2(t2v, NKK2, d62); nPi[p] = neg2(Pi[p]); }
                if (CLS == 3) { Pr[p] = fma2(t1v, NKK2, d04); nPi[p] = fma2(t2v, KK2, d62); Pi[p] = neg2(nPi[p]); }
                if (CLS == 5) { Pr[p] = fma2(t1v, NKK2, d04); Pi[p] = fma2(t2v, KK2, d62);  nPi[p] = neg2(Pi[p]); }
                if (CLS == 7) { Pr[p] = fma2(t1v, KK2, d04);  nPi[p] = fma2(t2v, NKK2, d62); Pi[p] = neg2(nPi[p]); }
            }
        }
#pragma unroll
        for (int k = 0; k < 8; k++) {
            ulonglong2 cs = ts2[idx[k]];
#pragma unroll
            for (int p = 0; p < 2; p++) {
                accR[k * 2 + p] = fma2(Pr[p], cs.x, accR[k * 2 + p]);
                accS[k * 2 + p] = fma2(Pr[p], cs.y, accS[k * 2 + p]);
                if (CLS != 0 && CLS != 4) {
                    accR[k * 2 + p] = fma2(Pi[p],  cs.y, accR[k * 2 + p]);
                    accS[k * 2 + p] = fma2(nPi[p], cs.x, accS[k * 2 + p]);
                }
            }
            idx[k] = (idx[k] + F[k]) & 4095;
        }
    }
}

// generic (mixed-class) fallback: per-mode class resolution from slots
static __device__ __forceinline__ void k1_chunk_gen(
    const ulonglong2* __restrict__ xs2, const ulonglong2* __restrict__ ts2,
    int lane, u64x accR[16], u64x accS[16], int idx[8], const int F[8])
{
    for (int tt = 0; tt < 8; tt++) {
        ulonglong2 S[8];
#pragma unroll
        for (int s = 0; s < 8; s++) S[s] = xs2[(s * 8 + tt) * 32 + lane];
#pragma unroll
        for (int k = 0; k < 8; k++) {
            int cls = F[k] & 7;
            u64x Pr[2], Pi[2], nPi[2];
#pragma unroll
            for (int p = 0; p < 2; p++) {
                u64x p0  = p ? S[0].y : S[0].x, p4  = p ? S[1].y : S[1].x;
                u64x p2r = p ? S[2].y : S[2].x, p2i = p ? S[3].y : S[3].x;
                u64x d04 = p ? S[4].y : S[4].x, d62 = p ? S[5].y : S[5].x;
                u64x t1v = p ? S[6].y : S[6].x, t2v = p ? S[7].y : S[7].x;
                switch (cls) {
                    case 0: Pr[p] = p0; Pi[p] = 0; break;
                    case 4: Pr[p] = p4; Pi[p] = 0; break;
                    case 2: Pr[p] = p2r; Pi[p] = p2i; break;
                    case 6: Pr[p] = p2r; Pi[p] = neg2(p2i); break;
                    case 1: Pr[p] = fma2(t1v, KK2, d04);  Pi[p] = fma2(t2v, NKK2, d62); break;
                    case 3: Pr[p] = fma2(t1v, NKK2, d04); Pi[p] = neg2(fma2(t2v, KK2, d62)); break;
                    case 5: Pr[p] = fma2(t1v, NKK2, d04); Pi[p] = fma2(t2v, KK2, d62); break;
                    default: Pr[p] = fma2(t1v, KK2, d04); Pi[p] = neg2(fma2(t2v, NKK2, d62)); break;
                }
                nPi[p] = neg2(Pi[p]);
            }
            ulonglong2 cs = ts2[idx[k]];
#pragma unroll
            for (int p = 0; p < 2; p++) {
                accR[k * 2 + p] = fma2(Pr[p], cs.x, accR[k * 2 + p]);
                accR[k * 2 + p] = fma2(Pi[p], cs.y, accR[k * 2 + p]);
                accS[k * 2 + p] = fma2(Pr[p], cs.y, accS[k * 2 + p]);
                accS[k * 2 + p] = fma2(nPi[p], cs.x, accS[k * 2 + p]);
            }
            idx[k] = (idx[k] + F[k]) & 4095;
        }
    }
}

#define K1_SMEM (4096 * 16 + 8 * 8 * 128 * 4 + 256)
__global__ void __launch_bounds__(256, 2) k1_forward(const float* __restrict__ qp,
                                                     const float* __restrict__ kp,
                                                     const int* __restrict__ iq,
                                                     const int* __restrict__ ikv) {
    extern __shared__ char sm[];
    ulonglong2* ts2 = (ulonglong2*)sm;
    float* xs = (float*)(ts2 + 4096);            // [8 slot][8 t'][128 ch]
    int* sMi = (int*)(xs + 8 * 8 * 128);         // [64]
    const ulonglong2* xs2 = (const ulonglong2*)xs;
    ulonglong2* xsw = (ulonglong2*)xs;

    const int ctile = blockIdx.x, b = blockIdx.y;
    const int tensor = blockIdx.z >> 2, tq = blockIdx.z & 3;
    const float* src = tensor ? kp : qp;
    const int* idxarr = tensor ? ikv : iq;
    const int tid = threadIdx.x, lane = tid & 31, warp = tid >> 5;

    for (int i = tid; i < 4096; i += 256) ts2[i] = g_ts[i];

    // bucket 64 modes by class (F&7); warp takes bucketed block per SMSP-balancing perm
    const int wperm_tab[8] = {0, 4, 2, 6, 1, 3, 5, 7};
    const int gw = wperm_tab[warp];
    const unsigned FULL = 0xffffffffu;
    int Flo = idxarr[lane], Fhi = idxarr[lane + 32];
    int clo = Flo & 7, chi = Fhi & 7;
    unsigned mlo[8], mhi[8];
    int off[9]; off[0] = 0;
#pragma unroll
    for (int c = 0; c < 8; c++) {
        mlo[c] = __ballot_sync(FULL, clo == c);
        mhi[c] = __ballot_sync(FULL, chi == c);
    }
#pragma unroll
    for (int c = 0; c < 8; c++) off[c + 1] = off[c] + __popc(mlo[c]) + __popc(mhi[c]);
    unsigned lm = (1u << lane) - 1u;
    int p_lo = off[clo] + __popc(mlo[clo] & lm);
    int p_hi = off[chi] + __popc(mlo[chi]) + __popc(mhi[chi] & lm);
    int F[8];
#pragma unroll
    for (int k = 0; k < 8; k++) {
        int tpos = gw * 8 + k;
        unsigned ba = __ballot_sync(FULL, p_lo == tpos);
        unsigned bb = __ballot_sync(FULL, p_hi == tpos);
        int m = ba ? (__ffs(ba) - 1) : (32 + __ffs(bb) - 1);
        if (lane == 0) sMi[tpos] = m;
        F[k] = __shfl_sync(FULL, (m < 32) ? Flo : Fhi, m & 31);
    }
    int jcls = F[0] & 7;
    bool uni = true;
#pragma unroll
    for (int k = 1; k < 8; k++) uni = uni && ((F[k] & 7) == jcls);

    u64x accR[16], accS[16]; int idx[8];
#pragma unroll
    for (int k = 0; k < 16; k++) { accR[k] = 0; accS[k] = 0; }

    const float* base = src + (size_t)b * NL * NCH + ctile * 128;
    const int sc4 = tid & 31, stt = tid >> 3 >> 2;   // staging: c4 = tid&31, tt = tid>>5

    for (int cc = 0; cc < 16; cc++) {
        const int tp0 = tq * 128 + cc * 8;
        __syncthreads();
        {
            // stage + shared radix-8 butterfly: thread -> (tt, ch-quad)
            const float* gp = base + (size_t)(tp0 + stt) * NCH + sc4 * 4;
            ulonglong2 a[8];
#pragma unroll
            for (int m = 0; m < 8; m++)
                a[m] = *(const ulonglong2*)(gp + (size_t)m * 512 * NCH);
            u64x o0[2], o1[2], o2[2], o3[2], o4[2], o5[2], o6[2], o7[2];
#pragma unroll
            for (int p = 0; p < 2; p++) {
                u64x a0 = p ? a[0].y : a[0].x, a1 = p ? a[1].y : a[1].x;
                u64x a2 = p ? a[2].y : a[2].x, a3 = p ? a[3].y : a[3].x;
                u64x a4 = p ? a[4].y : a[4].x, a5 = p ? a[5].y : a[5].x;
                u64x a6 = p ? a[6].y : a[6].x, a7 = p ? a[7].y : a[7].x;
                u64x e04 = add2(a0, a4), d04 = sub2(a0, a4);
                u64x e26 = add2(a2, a6), d62 = sub2(a6, a2);
                u64x e15 = add2(a1, a5), s1 = sub2(a1, a5);
                u64x e37 = add2(a3, a7), s2 = sub2(a3, a7);
                u64x E = add2(e04, e26), O = add2(e15, e37);
                o0[p] = add2(E, O);          // P0
                o1[p] = sub2(E, O);          // P4
                o2[p] = sub2(e04, e26);      // P2r
                o3[p] = sub2(e37, e15);      // P2i
                o4[p] = d04;
                o5[p] = d62;
                o6[p] = sub2(s1, s2);        // t1
                o7[p] = add2(s1, s2);        // t2
            }
            xsw[(0 * 8 + stt) * 32 + sc4] = make_ulonglong2(o0[0], o0[1]);
            xsw[(1 * 8 + stt) * 32 + sc4] = make_ulonglong2(o1[0], o1[1]);
            xsw[(2 * 8 + stt) * 32 + sc4] = make_ulonglong2(o2[0], o2[1]);
            xsw[(3 * 8 + stt) * 32 + sc4] = make_ulonglong2(o3[0], o3[1]);
            xsw[(4 * 8 + stt) * 32 + sc4] = make_ulonglong2(o4[0], o4[1]);
            xsw[(5 * 8 + stt) * 32 + sc4] = make_ulonglong2(o5[0], o5[1]);
            xsw[(6 * 8 + stt) * 32 + sc4] = make_ulonglong2(o6[0], o6[1]);
            xsw[(7 * 8 + stt) * 32 + sc4] = make_ulonglong2(o7[0], o7[1]);
        }
        __syncthreads();
#pragma unroll
        for (int k = 0; k < 8; k++) idx[k] = (F[k] * tp0) & 4095;
        if (uni) {
            switch (jcls) {
                case 0: k1_chunk8<0>(xs2, ts2, lane, accR, accS, idx, F); break;
                case 1: k1_chunk8<1>(xs2, ts2, lane, accR, accS, idx, F); break;
                case 2: k1_chunk8<2>(xs2, ts2, lane, accR, accS, idx, F); break;
                case 3: k1_chunk8<3>(xs2, ts2, lane, accR, accS, idx, F); break;
                case 4: k1_chunk8<4>(xs2, ts2, lane, accR, accS, idx, F); break;
                case 5: k1_chunk8<5>(xs2, ts2, lane, accR, accS, idx, F); break;
                case 6: k1_chunk8<6>(xs2, ts2, lane, accR, accS, idx, F); break;
                default: k1_chunk8<7>(xs2, ts2, lane, accR, accS, idx, F); break;
            }
        } else {
            k1_chunk_gen(xs2, ts2, lane, accR, accS, idx, F);
        }
    }

    const int ch = ctile * 128 + lane * 4;
    float2* dst = g_F + ((size_t)((tq * 2 + tensor) * NB + b) * NM) * NCH;
#pragma unroll
    for (int k = 0; k < 8; k++) {
        float r0, r1, r2, r3, s0, s1, s2, s3;
        unpack2(accR[k * 2 + 0], r0, r1);
        unpack2(accS[k * 2 + 0], s0, s1);
        unpack2(accR[k * 2 + 1], r2, r3);
        unpack2(accS[k * 2 + 1], s2, s3);
        int mi = sMi[gw * 8 + k];
        float2* dp = &dst[(size_t)mi * NCH + ch];
        *(float4*)(dp)     = make_float4(r0, -s0, r1, -s1);
        *(float4*)(dp + 2) = make_float4(r2, -s2, r3, -s3);
    }
}

// ================= K2a: per-(b,h,xhalf) tanh attention, writes C =================
#define K2A_SMEM (32 * 64 * 8 + 64 * 65 * 8 + 64 * 33 * 8)
__global__ void __launch_bounds__(256, 3) k2a_attn() {
    extern __shared__ char sm[];
    float2* sFq  = (float2*)sm;              // [32 xl][64 e]
    float2* sFkT = sFq + 32 * 64;            // [64 e][65 y-pad]
    float2* sA   = sFkT + 64 * 65;           // [64 y][33 xl-pad]

    const int bh = blockIdx.x, b = bh >> 3, h = bh & 7;
    const int x0 = blockIdx.y * 32;
    const int tid = threadIdx.x;
    const size_t QSTR = (size_t)2 * NB * NM * NCH;

    for (int i = tid; i < 2048; i += 256) {
        int xl = i >> 6, e = i & 63;
        size_t o0 = ((size_t)(b) * NM + (x0 + xl)) * NCH + h * 64 + e;
        float2 a0 = g_F[o0], a1 = g_F[o0 + QSTR], a2 = g_F[o0 + 2 * QSTR], a3 = g_F[o0 + 3 * QSTR];
        sFq[xl * 64 + e] = make_float2(a0.x + a1.x + a2.x + a3.x, a0.y + a1.y + a2.y + a3.y);
    }
    for (int i = tid; i < 4096; i += 256) {
        int e = i & 63, f = i >> 6;
        size_t o0 = ((size_t)(NB + b) * NM + f) * NCH + h * 64 + e;
        float2 a0 = g_F[o0], a1 = g_F[o0 + QSTR], a2 = g_F[o0 + 2 * QSTR], a3 = g_F[o0 + 3 * QSTR];
        sFkT[e * 65 + f] = make_float2(a0.x + a1.x + a2.x + a3.x, a0.y + a1.y + a2.y + a3.y);
    }
    __syncthreads();

    // A[x][y] = tanh_c( sum_e Fq[e,x] * Fk[e,y] )
#pragma unroll 1
    for (int p = 0; p < 8; p++) {
        int i = p * 256 + tid, xl = i >> 6, y = i & 63;
        float re = 0.f, im = 0.f;
#pragma unroll 4
        for (int e = 0; e < 64; e++) {
            float2 a = sFq[xl * 64 + e];     // broadcast
            float2 c = sFkT[e * 65 + y];     // consecutive
            re += a.x * c.x - a.y * c.y;
            im += a.x * c.y + a.y * c.x;
        }
        sA[y * 33 + xl] = make_float2(tanhf(re), tanhf(im));
    }
    __syncthreads();

    // C[e][x] = sum_y A[x,y] * Fk[e,y] -> g_C
#pragma unroll 1
    for (int p = 0; p < 8; p++) {
        int i = p * 256 + tid, xl = i & 31, e = i >> 5;
        float re = 0.f, im = 0.f;
#pragma unroll 4
        for (int y = 0; y < 64; y++) {
            float2 a  = sA[y * 33 + xl];     // consecutive
            float2 kv = sFkT[e * 65 + y];    // broadcast
            re += a.x * kv.x - a.y * kv.y;
            im += a.x * kv.y + a.y * kv.x;
        }
        g_C[((size_t)(h * 8 + b) * 64 + e) * 64 + x0 + xl] = make_float2(re, im);
    }
}

// ================= K2b: weight contraction, w read exactly once =================
#define K2B_SMEM (8 * 64 * 4 * 8)
__global__ void __launch_bounds__(256, 4) k2b_wproj(const float* __restrict__ w1,
                                                    const float* __restrict__ w2,
                                                    const int* __restrict__ iq) {
    extern __shared__ char sm[];
    float2* sC = (float2*)sm;                // [8 b][64 e][4 xl]

    const int h = blockIdx.x, x0 = blockIdx.y * 4;
    const int tid = threadIdx.x;

    for (int i = tid; i < 2048; i += 256) {
        int xl = i & 3, e = (i >> 2) & 63, b = i >> 8;
        sC[(b * 64 + e) * 4 + xl] = g_C[((size_t)(h * 8 + b) * 64 + e) * 64 + x0 + xl];
    }
    __syncthreads();

    const int xl = tid & 3, x = x0 + xl, o = tid >> 2;
    float accR[8], accI[8];
#pragma unroll
    for (int b = 0; b < 8; b++) { accR[b] = 0.f; accI[b] = 0.f; }

    size_t wbase = (((size_t)h * 64) * 64 + o) * 64 + x;
#pragma unroll 4
    for (int e = 0; e < 64; e++) {
        float wr = w1[wbase + (size_t)e * 4096];
        float wi = w2[wbase + (size_t)e * 4096];
#pragma unroll
        for (int b = 0; b < 8; b++) {
            float2 c = sC[(b * 64 + e) * 4 + xl];
            accR[b] += c.x * wr - c.y * wi;
            accI[b] += c.x * wi + c.y * wr;
        }
    }

    int fx = iq[x];
    float s = ((fx == 0) || (fx == NL / 2) ? 1.0f : 2.0f) * 9.313225746154785e-10f; // 2^-30
#pragma unroll
    for (int b = 0; b < 8; b++) {
        int row = (b * 8 + h) * 64 + o;
        g_O[(size_t)row * NM + x] = make_float2(s * accR[b], -s * accI[b]);
    }
}

// ================= K3: inverse sparse DFT (radix-4, 128 rows/CTA, 4 rows/lane) =================
// S0 = (P0+P2)+O, S2 = (P0+P2)-O, S1 = (P0-P2)+R, S3 = (P0-P2)-R
// O = P1+P3, R = Q1-Q3;  P = A cc + B ss, Q = B cc - A ss
#define K3_SMEM (4096 * 16 + 32768 + 32768 + 128 * 65 * 4 + 64 * 8 + 64)
__global__ void __launch_bounds__(512, 1) k3_inverse(float* __restrict__ out,
                                                     const int* __restrict__ iq) {
    extern __shared__ char sm[];
    ulonglong2* ts2 = (ulonglong2*)sm;            // 64KB
    float* sA = (float*)(ts2 + 4096);             // [f][128 slots]
    float* sB = sA + 64 * 128;
    float* sT = sB + 64 * 128;                    // [128 rows][65]
    int2* sperm = (int2*)(sT + 128 * 65);
    int* soff = (int*)(sperm + 64);

    const int rt = blockIdx.x;                    // 32 row tiles of 128
    const int tq = blockIdx.y;                    // 4 t' quarters
    const int r0 = rt * 128;
    const int tid = threadIdx.x, lane = tid & 31, warp = tid >> 5;

    for (int i = tid; i < 4096; i += 512) ts2[i] = g_ts[i];
    // load g_O: slot layout so one LDS.128 per f gives rows (2l,2l+1,64+2l,64+2l+1)
    for (int i = tid; i < 8192; i += 512) {
        int rr = i >> 6, f = i & 63;
        float2 v = g_O[(size_t)(r0 + rr) * NM + f];
        int half = rr >> 6, pr = (rr & 63) >> 1, sl = half * 2 + (rr & 1);
        sA[f * 128 + pr * 4 + sl] = v.x;
        sB[f * 128 + pr * 4 + sl] = v.y;
    }
    if (warp == 0) {
        const unsigned FULL = 0xffffffffu;
        int Flo = iq[lane], Fhi = iq[lane + 32];
        int clo = Flo & 3, chi = Fhi & 3;
        unsigned mlo[4], mhi[4];
        int off[5]; off[0] = 0;
#pragma unroll
        for (int c = 0; c < 4; c++) {
            mlo[c] = __ballot_sync(FULL, clo == c);
            mhi[c] = __ballot_sync(FULL, chi == c);
        }
#pragma unroll
        for (int c = 0; c < 4; c++) off[c + 1] = off[c] + __popc(mlo[c]) + __popc(mhi[c]);
        unsigned lmm = (1u << lane) - 1u;
        int p_lo = off[clo] + __popc(mlo[clo] & lmm);
        int p_hi = off[chi] + __popc(mlo[chi]) + __popc(mhi[chi] & lmm);
        sperm[p_lo] = make_int2(lane, Flo);
        sperm[p_hi] = make_int2(lane + 32, Fhi);
        if (lane < 5) soff[lane] = off[lane];
    }
    __syncthreads();

    const ulonglong2* sAd = (const ulonglong2*)sA;   // 32 ulonglong2 per f
    const ulonglong2* sBd = (const ulonglong2*)sB;
    const int o0 = soff[0], o1 = soff[1], o2 = soff[2], o3 = soff[3], o4 = soff[4];

#pragma unroll 1
    for (int pass = 0; pass < 4; pass++) {
        const int t0 = tq * 256 + pass * 64 + warp * 4;
        u64x P0[8], P2[8], O[8], R[8];   // [j*2 + pack]
#pragma unroll
        for (int j = 0; j < 8; j++) { P0[j] = 0; P2[j] = 0; O[j] = 0; R[j] = 0; }

        // class 0 -> P0
#pragma unroll 2
        for (int pos = o0; pos < o1; pos++) {
            int2 pf = sperm[pos];
            ulonglong2 A = sAd[pf.x * 32 + lane], B = sBd[pf.x * 32 + lane];
            int id = (pf.y * t0) & 4095;
#pragma unroll
            for (int j = 0; j < 4; j++) {
                ulonglong2 cs = ts2[id];
                P0[j * 2 + 0] = fma2(A.x, cs.x, P0[j * 2 + 0]);  P0[j * 2 + 0] = fma2(B.x, cs.y, P0[j * 2 + 0]);
                P0[j * 2 + 1] = fma2(A.y, cs.x, P0[j * 2 + 1]);  P0[j * 2 + 1] = fma2(B.y, cs.y, P0[j * 2 + 1]);
                id = (id + pf.y) & 4095;
            }
        }
        // class 1 -> O += P, R += Q
#pragma unroll 2
        for (int pos = o1; pos < o2; pos++) {
            int2 pf = sperm[pos];
            ulonglong2 A = sAd[pf.x * 32 + lane], B = sBd[pf.x * 32 + lane];
            u64x nAx = neg2(A.x), nAy = neg2(A.y);
            int id = (pf.y * t0) & 4095;
#pragma unroll
            for (int j = 0; j < 4; j++) {
                ulonglong2 cs = ts2[id];
                O[j * 2 + 0] = fma2(A.x, cs.x, O[j * 2 + 0]);   O[j * 2 + 0] = fma2(B.x, cs.y, O[j * 2 + 0]);
                O[j * 2 + 1] = fma2(A.y, cs.x, O[j * 2 + 1]);   O[j * 2 + 1] = fma2(B.y, cs.y, O[j * 2 + 1]);
                R[j * 2 + 0] = fma2(B.x, cs.x, R[j * 2 + 0]);   R[j * 2 + 0] = fma2(nAx, cs.y, R[j * 2 + 0]);
                R[j * 2 + 1] = fma2(B.y, cs.x, R[j * 2 + 1]);   R[j * 2 + 1] = fma2(nAy, cs.y, R[j * 2 + 1]);
                id = (id + pf.y) & 4095;
            }
        }
        // class 2 -> P2
#pragma unroll 2
        for (int pos = o2; pos < o3; pos++) {
            int2 pf = sperm[pos];
            ulonglong2 A = sAd[pf.x * 32 + lane], B = sBd[pf.x * 32 + lane];
            int id = (pf.y * t0) & 4095;
#pragma unroll
            for (int j = 0; j < 4; j++) {
                ulonglong2 cs = ts2[id];
                P2[j * 2 + 0] = fma2(A.x, cs.x, P2[j * 2 + 0]);  P2[j * 2 + 0] = fma2(B.x, cs.y, P2[j * 2 + 0]);
                P2[j * 2 + 1] = fma2(A.y, cs.x, P2[j * 2 + 1]);  P2[j * 2 + 1] = fma2(B.y, cs.y, P2[j * 2 + 1]);
                id = (id + pf.y) & 4095;
            }
        }
        // class 3 -> O += P, R -= Q
#pragma unroll 2
        for (int pos = o3; pos < o4; pos++) {
            int2 pf = sperm[pos];
            ulonglong2 A = sAd[pf.x * 32 + lane], B = sBd[pf.x * 32 + lane];
            u64x nBx = neg2(B.x), nBy = neg2(B.y);
            int id = (pf.y * t0) & 4095;
#pragma unroll
            for (int j = 0; j < 4; j++) {
                ulonglong2 cs = ts2[id];
                O[j * 2 + 0] = fma2(A.x, cs.x, O[j * 2 + 0]);   O[j * 2 + 0] = fma2(B.x, cs.y, O[j * 2 + 0]);
                O[j * 2 + 1] = fma2(A.y, cs.x, O[j * 2 + 1]);   O[j * 2 + 1] = fma2(B.y, cs.y, O[j * 2 + 1]);
                R[j * 2 + 0] = fma2(nBx, cs.x, R[j * 2 + 0]);   R[j * 2 + 0] = fma2(A.x, cs.y, R[j * 2 + 0]);
                R[j * 2 + 1] = fma2(nBy, cs.x, R[j * 2 + 1]);   R[j * 2 + 1] = fma2(A.y, cs.y, R[j * 2 + 1]);
                id = (id + pf.y) & 4095;
            }
        }

        // reconstruct 4 quadrants, transpose through sT, store
#pragma unroll 1
        for (int m = 0; m < 4; m++) {
            __syncthreads();
#pragma unroll
            for (int j = 0; j < 4; j++) {
#pragma unroll
                for (int p = 0; p < 2; p++) {
                    u64x S;
                    u64x Ps = add2(P0[j * 2 + p], P2[j * 2 + p]);
                    u64x Pd = sub2(P0[j * 2 + p], P2[j * 2 + p]);
                    if (m == 0)      S = add2(Ps, O[j * 2 + p]);
                    else if (m == 1) S = add2(Pd, R[j * 2 + p]);
                    else if (m == 2) S = sub2(Ps, O[j * 2 + p]);
                    else             S = sub2(Pd, R[j * 2 + p]);
                    float v0, v1;
                    unpack2(S, v0, v1);
                    int tl = warp * 4 + j;
                    int rbase = p * 64 + 2 * lane;
                    sT[rbase * 65 + tl]       = v0;
                    sT[(rbase + 1) * 65 + tl] = v1;
                }
            }
            __syncthreads();
            int tbase = m * 1024 + tq * 256 + pass * 64;
#pragma unroll
            for (int ii = 0; ii < 4; ii++) {
                int i = ii * 512 + tid;        // 2048 float4
                int rr = i >> 4, c4 = i & 15;
                const float* sp = sT + rr * 65 + c4 * 4;
                float4 vv = make_float4(sp[0], sp[1], sp[2], sp[3]);
                *(float4*)&out[(size_t)(r0 + rr) * NL + tbase + c4 * 4] = vv;
            }
        }
    }
}

// ================= launch =================
extern "C" void kernel_launch(void* const* d_in, const int* in_sizes, int n_in,
                              void* d_out, int out_size) {
    const float* q  = (const float*)d_in[0];
    const float* k  = (const float*)d_in[1];
    // d_in[2] = v, never used by the reference
    const float* w1 = (const float*)d_in[3];
    const float* w2 = (const float*)d_in[4];
    const int* iq   = (const int*)d_in[5];
    const int* ikv  = (const int*)d_in[6];
    float* out = (float*)d_out;

    cudaFuncSetAttribute(k1_forward, cudaFuncAttributeMaxDynamicSharedMemorySize, K1_SMEM);
    cudaFuncSetAttribute(k2a_attn,   cudaFuncAttributeMaxDynamicSharedMemorySize, K2A_SMEM);
    cudaFuncSetAttribute(k2b_wproj,  cudaFuncAttributeMaxDynamicSharedMemorySize, K2B_SMEM);
    cudaFuncSetAttribute(k3_inverse, cudaFuncAttributeMaxDynamicSharedMemorySize, K3_SMEM);

    k0_init<<<16, 256>>>();
    k1_forward<<<dim3(4, NB, 8), 256, K1_SMEM>>>(q, k, iq, ikv);
    k2a_attn<<<dim3(NB * NH, 2), 256, K2A_SMEM>>>();
    k2b_wproj<<<dim3(NH, 16), 256, K2B_SMEM>>>(w1, w2, iq);
    k3_inverse<<<dim3(32, 4), 512, K3_SMEM>>>(out, iq);
}

// round 12
// speedup vs baseline: 1.3400x; 1.0003x over previous
#include <cuda_runtime.h>
#include <math.h>

#define NB 8
#define NL 4096
#define NH 8
#define NM 64
#define NCH 512

typedef unsigned long long u64x;

// ---------------- device scratch ----------------
__device__ ulonglong2 g_ts[4096];                  // (cc, ss) packed f32x2 of angle 2*pi*i/4096
__device__ float2 g_F[8 * NB * NM * NCH];          // [tq*2+tensor][b][mode-pos][ch]
__device__ float2 g_C[NB * NH * 64 * 64];          // [(h*8+b)][e][x] complex
__device__ float2 g_O[NB * NH * 64 * NM];          // [row][mode-pos]: (A, B) pre-scaled

// ---------------- f32x2 helpers ----------------
static __device__ __forceinline__ u64x fma2(u64x a, u64x b, u64x c) {
    u64x d; asm("fma.rn.f32x2 %0,%1,%2,%3;" : "=l"(d) : "l"(a), "l"(b), "l"(c)); return d;
}
static __device__ __forceinline__ u64x add2(u64x a, u64x b) {
    u64x d; asm("add.rn.f32x2 %0,%1,%2;" : "=l"(d) : "l"(a), "l"(b)); return d;
}
#define NEG1X2 0xBF800000BF800000ULL
#define KK2    0x3F3504F33F3504F3ULL   // (sqrt2/2, sqrt2/2)
#define NKK2   0xBF3504F3BF3504F3ULL   // negated
static __device__ __forceinline__ u64x sub2(u64x a, u64x b) { return fma2(b, NEG1X2, a); }
static __device__ __forceinline__ u64x neg2(u64x a) { return fma2(a, NEG1X2, 0ULL); }
static __device__ __forceinline__ void unpack2(u64x d, float& lo, float& hi) {
    asm("mov.b64 {%0,%1},%2;" : "=f"(lo), "=f"(hi) : "l"(d));
}

// ================= K0: trig table =================
__global__ void k0_init() {
    int i = blockIdx.x * 256 + threadIdx.x;
    if (i < 4096) {
        float s, c;
        sincospif((float)i / 2048.0f, &s, &c);
        u64x cc, ss;
        asm("mov.b64 %0,{%1,%1};" : "=l"(cc) : "f"(c));
        asm("mov.b64 %0,{%1,%1};" : "=l"(ss) : "f"(s));
        g_ts[i] = make_ulonglong2(cc, ss);
    }
}

// ================= K1: forward sparse DFT (radix-8, shared butterfly in staging) =================
// X[f] = sum_{t'} u_j(t') e^{-i 2pi f t'/4096}, j=f&7, u_j = sum_m x[t'+512m] w^{jm}, w=e^{-i pi/4}.
// Staging computes per (t', ch): slots {P0,P4,P2r,P2i,d04,d62,t1,t2}; classes read only their slots:
//   u0 = P0 ; u4 = P4 ; u2 = P2r + i P2i ; u6 = P2r - i P2i
//   u1 = (d04 + k t1) + i(d62 - k t2) ; u3 = (d04 - k t1) - i(d62 + k t2)
//   u5 = (d04 - k t1) + i(d62 + k t2) ; u7 = (d04 + k t1) + i(k t2 - d62)    (k = sqrt2/2)
// accR=Re, accS accumulates -Im: accR += Pr*cc + Pi*ss ; accS += Pr*ss - Pi*cc.
template<int CLS>
static __device__ __forceinline__ void k1_chunk8(
    const ulonglong2* __restrict__ xs2, const ulonglong2* __restrict__ ts2,
    int lane, u64x accR[16], u64x accS[16], int idx[8], const int F[8])
{
#pragma unroll 2
    for (int tt = 0; tt < 8; tt++) {
        u64x Pr[2], Pi[2], nPi[2];
        if (CLS == 0) {
            ulonglong2 X = xs2[(0 * 8 + tt) * 32 + lane];
            Pr[0] = X.x; Pr[1] = X.y;
        } else if (CLS == 4) {
            ulonglong2 X = xs2[(1 * 8 + tt) * 32 + lane];
            Pr[0] = X.x; Pr[1] = X.y;
        } else if (CLS == 2) {
            ulonglong2 XR = xs2[(2 * 8 + tt) * 32 + lane];
            ulonglong2 XI = xs2[(3 * 8 + tt) * 32 + lane];
            Pr[0] = XR.x; Pr[1] = XR.y;
            Pi[0] = XI.x; Pi[1] = XI.y;
            nPi[0] = neg2(Pi[0]); nPi[1] = neg2(Pi[1]);
        } else if (CLS == 6) {
            ulonglong2 XR = xs2[(2 * 8 + tt) * 32 + lane];
            ulonglong2 XI = xs2[(3 * 8 + tt) * 32 + lane];
            Pr[0] = XR.x; Pr[1] = XR.y;
            nPi[0] = XI.x; nPi[1] = XI.y;
            Pi[0] = neg2(nPi[0]); Pi[1] = neg2(nPi[1]);
        } else {
            ulonglong2 D04 = xs2[(4 * 8 + tt) * 32 + lane];
            ulonglong2 D62 = xs2[(5 * 8 + tt) * 32 + lane];
            ulonglong2 T1  = xs2[(6 * 8 + tt) * 32 + lane];
            ulonglong2 T2  = xs2[(7 * 8 + tt) * 32 + lane];
#pragma unroll
            for (int p = 0; p < 2; p++) {
                u64x d04 = p ? D04.y : D04.x;
                u64x d62 = p ? D62.y : D62.x;
                u64x t1v = p ? T1.y : T1.x;
                u64x t2v = p ? T2.y : T2.x;
                if (CLS == 1) { Pr[p] = fma2(t1v, KK2, d04);  Pi[p] = fma2(t2v, NKK2, d62); nPi[p] = neg2(Pi[p]); }
                if (CLS == 3) { Pr[p] = fma2(t1v, NKK2, d04); nPi[p] = fma2(t2v, KK2, d62); Pi[p] = neg2(nPi[p]); }
                if (CLS == 5) { Pr[p] = fma2(t1v, NKK2, d04); Pi[p] = fma2(t2v, KK2, d62);  nPi[p] = neg2(Pi[p]); }
                if (CLS == 7) { Pr[p] = fma2(t1v, KK2, d04);  nPi[p] = fma2(t2v, NKK2, d62); Pi[p] = neg2(nPi[p]); }
            }
        }
#pragma unroll
        for (int k = 0; k < 8; k++) {
            ulonglong2 cs = ts2[idx[k]];
#pragma unroll
            for (int p = 0; p < 2; p++) {
                accR[k * 2 + p] = fma2(Pr[p], cs.x, accR[k * 2 + p]);
                accS[k * 2 + p] = fma2(Pr[p], cs.y, accS[k * 2 + p]);
                if (CLS != 0 && CLS != 4) {
                    accR[k * 2 + p] = fma2(Pi[p],  cs.y, accR[k * 2 + p]);
                    accS[k * 2 + p] = fma2(nPi[p], cs.x, accS[k * 2 + p]);
                }
            }
            idx[k] = (idx[k] + F[k]) & 4095;
        }
    }
}

// generic (mixed-class) fallback: per-mode class resolution from slots
static __device__ __forceinline__ void k1_chunk_gen(
    const ulonglong2* __restrict__ xs2, const ulonglong2* __restrict__ ts2,
    int lane, u64x accR[16], u64x accS[16], int idx[8], const int F[8])
{
    for (int tt = 0; tt < 8; tt++) {
        ulonglong2 S[8];
#pragma unroll
        for (int s = 0; s < 8; s++) S[s] = xs2[(s * 8 + tt) * 32 + lane];
#pragma unroll
        for (int k = 0; k < 8; k++) {
            int cls = F[k] & 7;
            u64x Pr[2], Pi[2], nPi[2];
#pragma unroll
            for (int p = 0; p < 2; p++) {
                u64x p0  = p ? S[0].y : S[0].x, p4  = p ? S[1].y : S[1].x;
                u64x p2r = p ? S[2].y : S[2].x, p2i = p ? S[3].y : S[3].x;
                u64x d04 = p ? S[4].y : S[4].x, d62 = p ? S[5].y : S[5].x;
                u64x t1v = p ? S[6].y : S[6].x, t2v = p ? S[7].y : S[7].x;
                switch (cls) {
                    case 0: Pr[p] = p0; Pi[p] = 0; break;
                    case 4: Pr[p] = p4; Pi[p] = 0; break;
                    case 2: Pr[p] = p2r; Pi[p] = p2i; break;
                    case 6: Pr[p] = p2r; Pi[p] = neg2(p2i); break;
                    case 1: Pr[p] = fma2(t1v, KK2, d04);  Pi[p] = fma2(t2v, NKK2, d62); break;
                    case 3: Pr[p] = fma2(t1v, NKK2, d04); Pi[p] = neg2(fma2(t2v, KK2, d62)); break;
                    case 5: Pr[p] = fma2(t1v, NKK2, d04); Pi[p] = fma2(t2v, KK2, d62); break;
                    default: Pr[p] = fma2(t1v, KK2, d04); Pi[p] = neg2(fma2(t2v, NKK2, d62)); break;
                }
                nPi[p] = neg2(Pi[p]);
            }
            ulonglong2 cs = ts2[idx[k]];
#pragma unroll
            for (int p = 0; p < 2; p++) {
                accR[k * 2 + p] = fma2(Pr[p], cs.x, accR[k * 2 + p]);
                accR[k * 2 + p] = fma2(Pi[p], cs.y, accR[k * 2 + p]);
                accS[k * 2 + p] = fma2(Pr[p], cs.y, accS[k * 2 + p]);
                accS[k * 2 + p] = fma2(nPi[p], cs.x, accS[k * 2 + p]);
            }
            idx[k] = (idx[k] + F[k]) & 4095;
        }
    }
}

#define K1_SMEM (4096 * 16 + 8 * 8 * 128 * 4 + 256)
__global__ void __launch_bounds__(256, 2) k1_forward(const float* __restrict__ qp,
                                                     const float* __restrict__ kp,
                                                     const int* __restrict__ iq,
                                                     const int* __restrict__ ikv) {
    extern __shared__ char sm[];
    ulonglong2* ts2 = (ulonglong2*)sm;
    float* xs = (float*)(ts2 + 4096);            // [8 slot][8 t'][128 ch]
    int* sMi = (int*)(xs + 8 * 8 * 128);         // [64]
    const ulonglong2* xs2 = (const ulonglong2*)xs;
    ulonglong2* xsw = (ulonglong2*)xs;

    const int ctile = blockIdx.x, b = blockIdx.y;
    const int tensor = blockIdx.z >> 2, tq = blockIdx.z & 3;
    const float* src = tensor ? kp : qp;
    const int* idxarr = tensor ? ikv : iq;
    const int tid = threadIdx.x, lane = tid & 31, warp = tid >> 5;

    for (int i = tid; i < 4096; i += 256) ts2[i] = g_ts[i];

    // bucket 64 modes by class (F&7); warp takes bucketed block per SMSP-balancing perm
    const int wperm_tab[8] = {0, 4, 2, 6, 1, 3, 5, 7};
    const int gw = wperm_tab[warp];
    const unsigned FULL = 0xffffffffu;
    int Flo = idxarr[lane], Fhi = idxarr[lane + 32];
    int clo = Flo & 7, chi = Fhi & 7;
    unsigned mlo[8], mhi[8];
    int off[9]; off[0] = 0;
#pragma unroll
    for (int c = 0; c < 8; c++) {
        mlo[c] = __ballot_sync(FULL, clo == c);
        mhi[c] = __ballot_sync(FULL, chi == c);
    }
#pragma unroll
    for (int c = 0; c < 8; c++) off[c + 1] = off[c] + __popc(mlo[c]) + __popc(mhi[c]);
    unsigned lm = (1u << lane) - 1u;
    int p_lo = off[clo] + __popc(mlo[clo] & lm);
    int p_hi = off[chi] + __popc(mlo[chi]) + __popc(mhi[chi] & lm);
    int F[8];
#pragma unroll
    for (int k = 0; k < 8; k++) {
        int tpos = gw * 8 + k;
        unsigned ba = __ballot_sync(FULL, p_lo == tpos);
        unsigned bb = __ballot_sync(FULL, p_hi == tpos);
        int m = ba ? (__ffs(ba) - 1) : (32 + __ffs(bb) - 1);
        if (lane == 0) sMi[tpos] = m;
        F[k] = __shfl_sync(FULL, (m < 32) ? Flo : Fhi, m & 31);
    }
    int jcls = F[0] & 7;
    bool uni = true;
#pragma unroll
    for (int k = 1; k < 8; k++) uni = uni && ((F[k] & 7) == jcls);

    u64x accR[16], accS[16]; int idx[8];
#pragma unroll
    for (int k = 0; k < 16; k++) { accR[k] = 0; accS[k] = 0; }

    const float* base = src + (size_t)b * NL * NCH + ctile * 128;
    const int sc4 = tid & 31, stt = tid >> 3 >> 2;   // staging: c4 = tid&31, tt = tid>>5

    for (int cc = 0; cc < 16; cc++) {
        const int tp0 = tq * 128 + cc * 8;
        __syncthreads();
        {
            // stage + shared radix-8 butterfly: thread -> (tt, ch-quad)
            const float* gp = base + (size_t)(tp0 + stt) * NCH + sc4 * 4;
            ulonglong2 a[8];
#pragma unroll
            for (int m = 0; m < 8; m++)
                a[m] = *(const ulonglong2*)(gp + (size_t)m * 512 * NCH);
            u64x o0[2], o1[2], o2[2], o3[2], o4[2], o5[2], o6[2], o7[2];
#pragma unroll
            for (int p = 0; p < 2; p++) {
                u64x a0 = p ? a[0].y : a[0].x, a1 = p ? a[1].y : a[1].x;
                u64x a2 = p ? a[2].y : a[2].x, a3 = p ? a[3].y : a[3].x;
                u64x a4 = p ? a[4].y : a[4].x, a5 = p ? a[5].y : a[5].x;
                u64x a6 = p ? a[6].y : a[6].x, a7 = p ? a[7].y : a[7].x;
                u64x e04 = add2(a0, a4), d04 = sub2(a0, a4);
                u64x e26 = add2(a2, a6), d62 = sub2(a6, a2);
                u64x e15 = add2(a1, a5), s1 = sub2(a1, a5);
                u64x e37 = add2(a3, a7), s2 = sub2(a3, a7);
                u64x E = add2(e04, e26), O = add2(e15, e37);
                o0[p] = add2(E, O);          // P0
                o1[p] = sub2(E, O);          // P4
                o2[p] = sub2(e04, e26);      // P2r
                o3[p] = sub2(e37, e15);      // P2i
                o4[p] = d04;
                o5[p] = d62;
                o6[p] = sub2(s1, s2);        // t1
                o7[p] = add2(s1, s2);        // t2
            }
            xsw[(0 * 8 + stt) * 32 + sc4] = make_ulonglong2(o0[0], o0[1]);
            xsw[(1 * 8 + stt) * 32 + sc4] = make_ulonglong2(o1[0], o1[1]);
            xsw[(2 * 8 + stt) * 32 + sc4] = make_ulonglong2(o2[0], o2[1]);
            xsw[(3 * 8 + stt) * 32 + sc4] = make_ulonglong2(o3[0], o3[1]);
            xsw[(4 * 8 + stt) * 32 + sc4] = make_ulonglong2(o4[0], o4[1]);
            xsw[(5 * 8 + stt) * 32 + sc4] = make_ulonglong2(o5[0], o5[1]);
            xsw[(6 * 8 + stt) * 32 + sc4] = make_ulonglong2(o6[0], o6[1]);
            xsw[(7 * 8 + stt) * 32 + sc4] = make_ulonglong2(o7[0], o7[1]);
        }
        __syncthreads();
#pragma unroll
        for (int k = 0; k < 8; k++) idx[k] = (F[k] * tp0) & 4095;
        if (uni) {
            switch (jcls) {
                case 0: k1_chunk8<0>(xs2, ts2, lane, accR, accS, idx, F); break;
                case 1: k1_chunk8<1>(xs2, ts2, lane, accR, accS, idx, F); break;
                case 2: k1_chunk8<2>(xs2, ts2, lane, accR, accS, idx, F); break;
                case 3: k1_chunk8<3>(xs2, ts2, lane, accR, accS, idx, F); break;
                case 4: k1_chunk8<4>(xs2, ts2, lane, accR, accS, idx, F); break;
                case 5: k1_chunk8<5>(xs2, ts2, lane, accR, accS, idx, F); break;
                case 6: k1_chunk8<6>(xs2, ts2, lane, accR, accS, idx, F); break;
                default: k1_chunk8<7>(xs2, ts2, lane, accR, accS, idx, F); break;
            }
        } else {
            k1_chunk_gen(xs2, ts2, lane, accR, accS, idx, F);
        }
    }

    const int ch = ctile * 128 + lane * 4;
    float2* dst = g_F + ((size_t)((tq * 2 + tensor) * NB + b) * NM) * NCH;
#pragma unroll
    for (int k = 0; k < 8; k++) {
        float r0, r1, r2, r3, s0, s1, s2, s3;
        unpack2(accR[k * 2 + 0], r0, r1);
        unpack2(accS[k * 2 + 0], s0, s1);
        unpack2(accR[k * 2 + 1], r2, r3);
        unpack2(accS[k * 2 + 1], s2, s3);
        int mi = sMi[gw * 8 + k];
        float2* dp = &dst[(size_t)mi * NCH + ch];
        *(float4*)(dp)     = make_float4(r0, -s0, r1, -s1);
        *(float4*)(dp + 2) = make_float4(r2, -s2, r3, -s3);
    }
}

// ================= K2a: per-(b,h,xhalf) tanh attention, writes C =================
#define K2A_SMEM (32 * 64 * 8 + 64 * 65 * 8 + 64 * 33 * 8)
__global__ void __launch_bounds__(256, 3) k2a_attn() {
    extern __shared__ char sm[];
    float2* sFq  = (float2*)sm;              // [32 xl][64 e]
    float2* sFkT = sFq + 32 * 64;            // [64 e][65 y-pad]
    float2* sA   = sFkT + 64 * 65;           // [64 y][33 xl-pad]

    const int bh = blockIdx.x, b = bh >> 3, h = bh & 7;
    const int x0 = blockIdx.y * 32;
    const int tid = threadIdx.x;
    const size_t QSTR = (size_t)2 * NB * NM * NCH;

    for (int i = tid; i < 2048; i += 256) {
        int xl = i >> 6, e = i & 63;
        size_t o0 = ((size_t)(b) * NM + (x0 + xl)) * NCH + h * 64 + e;
        float2 a0 = g_F[o0], a1 = g_F[o0 + QSTR], a2 = g_F[o0 + 2 * QSTR], a3 = g_F[o0 + 3 * QSTR];
        sFq[xl * 64 + e] = make_float2(a0.x + a1.x + a2.x + a3.x, a0.y + a1.y + a2.y + a3.y);
    }
    for (int i = tid; i < 4096; i += 256) {
        int e = i & 63, f = i >> 6;
        size_t o0 = ((size_t)(NB + b) * NM + f) * NCH + h * 64 + e;
        float2 a0 = g_F[o0], a1 = g_F[o0 + QSTR], a2 = g_F[o0 + 2 * QSTR], a3 = g_F[o0 + 3 * QSTR];
        sFkT[e * 65 + f] = make_float2(a0.x + a1.x + a2.x + a3.x, a0.y + a1.y + a2.y + a3.y);
    }
    __syncthreads();

    // A[x][y] = tanh_c( sum_e Fq[e,x] * Fk[e,y] )
#pragma unroll 1
    for (int p = 0; p < 8; p++) {
        int i = p * 256 + tid, xl = i >> 6, y = i & 63;
        float re = 0.f, im = 0.f;
#pragma unroll 4
        for (int e = 0; e < 64; e++) {
            float2 a = sFq[xl * 64 + e];     // broadcast
            float2 c = sFkT[e * 65 + y];     // consecutive
            re += a.x * c.x - a.y * c.y;
            im += a.x * c.y + a.y * c.x;
        }
        sA[y * 33 + xl] = make_float2(tanhf(re), tanhf(im));
    }
    __syncthreads();

    // C[e][x] = sum_y A[x,y] * Fk[e,y] -> g_C
#pragma unroll 1
    for (int p = 0; p < 8; p++) {
        int i = p * 256 + tid, xl = i & 31, e = i >> 5;
        float re = 0.f, im = 0.f;
#pragma unroll 4
        for (int y = 0; y < 64; y++) {
            float2 a  = sA[y * 33 + xl];     // consecutive
            float2 kv = sFkT[e * 65 + y];    // broadcast
            re += a.x * kv.x - a.y * kv.y;
            im += a.x * kv.y + a.y * kv.x;
        }
        g_C[((size_t)(h * 8 + b) * 64 + e) * 64 + x0 + xl] = make_float2(re, im);
    }
}

// ================= K2b: weight contraction, w read exactly once =================
#define K2B_SMEM (8 * 64 * 4 * 8)
__global__ void __launch_bounds__(256, 4) k2b_wproj(const float* __restrict__ w1,
                                                    const float* __restrict__ w2,
                                                    const int* __restrict__ iq) {
    extern __shared__ char sm[];
    float2* sC = (float2*)sm;                // [8 b][64 e][4 xl]

    const int h = blockIdx.x, x0 = blockIdx.y * 4;
    const int tid = threadIdx.x;

    for (int i = tid; i < 2048; i += 256) {
        int xl = i & 3, e = (i >> 2) & 63, b = i >> 8;
        sC[(b * 64 + e) * 4 + xl] = g_C[((size_t)(h * 8 + b) * 64 + e) * 64 + x0 + xl];
    }
    __syncthreads();

    const int xl = tid & 3, x = x0 + xl, o = tid >> 2;
    float accR[8], accI[8];
#pragma unroll
    for (int b = 0; b < 8; b++) { accR[b] = 0.f; accI[b] = 0.f; }

    size_t wbase = (((size_t)h * 64) * 64 + o) * 64 + x;
#pragma unroll 4
    for (int e = 0; e < 64; e++) {
        float wr = w1[wbase + (size_t)e * 4096];
        float wi = w2[wbase + (size_t)e * 4096];
#pragma unroll
        for (int b = 0; b < 8; b++) {
            float2 c = sC[(b * 64 + e) * 4 + xl];
            accR[b] += c.x * wr - c.y * wi;
            accI[b] += c.x * wi + c.y * wr;
        }
    }

    int fx = iq[x];
    float s = ((fx == 0) || (fx == NL / 2) ? 1.0f : 2.0f) * 9.313225746154785e-10f; // 2^-30
#pragma unroll
    for (int b = 0; b < 8; b++) {
        int row = (b * 8 + h) * 64 + o;
        g_O[(size_t)row * NM + x] = make_float2(s * accR[b], -s * accI[b]);
    }
}

// ================= K3: inverse sparse DFT (radix-4, 128 rows/CTA, 4 rows/lane) =================
// S0 = (P0+P2)+O, S2 = (P0+P2)-O, S1 = (P0-P2)+R, S3 = (P0-P2)-R
// O = P1+P3, R = Q1-Q3;  P = A cc + B ss, Q = B cc - A ss
#define K3_SMEM (4096 * 16 + 32768 + 32768 + 128 * 65 * 4 + 64 * 8 + 64)
__global__ void __launch_bounds__(512, 1) k3_inverse(float* __restrict__ out,
                                                     const int* __restrict__ iq) {
    extern __shared__ char sm[];
    ulonglong2* ts2 = (ulonglong2*)sm;            // 64KB
    float* sA = (float*)(ts2 + 4096);             // [f][128 slots]
    float* sB = sA + 64 * 128;
    float* sT = sB + 64 * 128;                    // [128 rows][65]
    int2* sperm = (int2*)(sT + 128 * 65);
    int* soff = (int*)(sperm + 64);

    const int rt = blockIdx.x;                    // 32 row tiles of 128
    const int tq = blockIdx.y;                    // 4 t' quarters
    const int r0 = rt * 128;
    const int tid = threadIdx.x, lane = tid & 31, warp = tid >> 5;

    for (int i = tid; i < 4096; i += 512) ts2[i] = g_ts[i];
    // load g_O: slot layout so one LDS.128 per f gives rows (2l,2l+1,64+2l,64+2l+1)
    for (int i = tid; i < 8192; i += 512) {
        int rr = i >> 6, f = i & 63;
        float2 v = g_O[(size_t)(r0 + rr) * NM + f];
        int half = rr >> 6, pr = (rr & 63) >> 1, sl = half * 2 + (rr & 1);
        sA[f * 128 + pr * 4 + sl] = v.x;
        sB[f * 128 + pr * 4 + sl] = v.y;
    }
    if (warp == 0) {
        const unsigned FULL = 0xffffffffu;
        int Flo = iq[lane], Fhi = iq[lane + 32];
        int clo = Flo & 3, chi = Fhi & 3;
        unsigned mlo[4], mhi[4];
        int off[5]; off[0] = 0;
#pragma unroll
        for (int c = 0; c < 4; c++) {
            mlo[c] = __ballot_sync(FULL, clo == c);
            mhi[c] = __ballot_sync(FULL, chi == c);
        }
#pragma unroll
        for (int c = 0; c < 4; c++) off[c + 1] = off[c] + __popc(mlo[c]) + __popc(mhi[c]);
        unsigned lmm = (1u << lane) - 1u;
        int p_lo = off[clo] + __popc(mlo[clo] & lmm);
        int p_hi = off[chi] + __popc(mlo[chi]) + __popc(mhi[chi] & lmm);
        sperm[p_lo] = make_int2(lane, Flo);
        sperm[p_hi] = make_int2(lane + 32, Fhi);
        if (lane < 5) soff[lane] = off[lane];
    }
    __syncthreads();

    const ulonglong2* sAd = (const ulonglong2*)sA;   // 32 ulonglong2 per f
    const ulonglong2* sBd = (const ulonglong2*)sB;
    const int o0 = soff[0], o1 = soff[1], o2 = soff[2], o3 = soff[3], o4 = soff[4];

#pragma unroll 1
    for (int pass = 0; pass < 4; pass++) {
        const int t0 = tq * 256 + pass * 64 + warp * 4;
        u64x P0[8], P2[8], O[8], R[8];   // [j*2 + pack]
#pragma unroll
        for (int j = 0; j < 8; j++) { P0[j] = 0; P2[j] = 0; O[j] = 0; R[j] = 0; }

        // class 0 -> P0
#pragma unroll 2
        for (int pos = o0; pos < o1; pos++) {
            int2 pf = sperm[pos];
            ulonglong2 A = sAd[pf.x * 32 + lane], B = sBd[pf.x * 32 + lane];
            int id = (pf.y * t0) & 4095;
#pragma unroll
            for (int j = 0; j < 4; j++) {
                ulonglong2 cs = ts2[id];
                P0[j * 2 + 0] = fma2(A.x, cs.x, P0[j * 2 + 0]);  P0[j * 2 + 0] = fma2(B.x, cs.y, P0[j * 2 + 0]);
                P0[j * 2 + 1] = fma2(A.y, cs.x, P0[j * 2 + 1]);  P0[j * 2 + 1] = fma2(B.y, cs.y, P0[j * 2 + 1]);
                id = (id + pf.y) & 4095;
            }
        }
        // class 1 -> O += P, R += Q
#pragma unroll 2
        for (int pos = o1; pos < o2; pos++) {
            int2 pf = sperm[pos];
            ulonglong2 A = sAd[pf.x * 32 + lane], B = sBd[pf.x * 32 + lane];
            u64x nAx = neg2(A.x), nAy = neg2(A.y);
            int id = (pf.y * t0) & 4095;
#pragma unroll
            for (int j = 0; j < 4; j++) {
                ulonglong2 cs = ts2[id];
                O[j * 2 + 0] = fma2(A.x, cs.x, O[j * 2 + 0]);   O[j * 2 + 0] = fma2(B.x, cs.y, O[j * 2 + 0]);
                O[j * 2 + 1] = fma2(A.y, cs.x, O[j * 2 + 1]);   O[j * 2 + 1] = fma2(B.y, cs.y, O[j * 2 + 1]);
                R[j * 2 + 0] = fma2(B.x, cs.x, R[j * 2 + 0]);   R[j * 2 + 0] = fma2(nAx, cs.y, R[j * 2 + 0]);
                R[j * 2 + 1] = fma2(B.y, cs.x, R[j * 2 + 1]);   R[j * 2 + 1] = fma2(nAy, cs.y, R[j * 2 + 1]);
                id = (id + pf.y) & 4095;
            }
        }
        // class 2 -> P2
#pragma unroll 2
        for (int pos = o2; pos < o3; pos++) {
            int2 pf = sperm[pos];
            ulonglong2 A = sAd[pf.x * 32 + lane], B = sBd[pf.x * 32 + lane];
            int id = (pf.y * t0) & 4095;
#pragma unroll
            for (int j = 0; j < 4; j++) {
                ulonglong2 cs = ts2[id];
                P2[j * 2 + 0] = fma2(A.x, cs.x, P2[j * 2 + 0]);  P2[j * 2 + 0] = fma2(B.x, cs.y, P2[j * 2 + 0]);
                P2[j * 2 + 1] = fma2(A.y, cs.x, P2[j * 2 + 1]);  P2[j * 2 + 1] = fma2(B.y, cs.y, P2[j * 2 + 1]);
                id = (id + pf.y) & 4095;
            }
        }
        // class 3 -> O += P, R -= Q
#pragma unroll 2
        for (int pos = o3; pos < o4; pos++) {
            int2 pf = sperm[pos];
            ulonglong2 A = sAd[pf.x * 32 + lane], B = sBd[pf.x * 32 + lane];
            u64x nBx = neg2(B.x), nBy = neg2(B.y);
            int id = (pf.y * t0) & 4095;
#pragma unroll
            for (int j = 0; j < 4; j++) {
                ulonglong2 cs = ts2[id];
                O[j * 2 + 0] = fma2(A.x, cs.x, O[j * 2 + 0]);   O[j * 2 + 0] = fma2(B.x, cs.y, O[j * 2 + 0]);
                O[j * 2 + 1] = fma2(A.y, cs.x, O[j * 2 + 1]);   O[j * 2 + 1] = fma2(B.y, cs.y, O[j * 2 + 1]);
                R[j * 2 + 0] = fma2(nBx, cs.x, R[j * 2 + 0]);   R[j * 2 + 0] = fma2(A.x, cs.y, R[j * 2 + 0]);
                R[j * 2 + 1] = fma2(nBy, cs.x, R[j * 2 + 1]);   R[j * 2 + 1] = fma2(A.y, cs.y, R[j * 2 + 1]);
                id = (id + pf.y) & 4095;
            }
        }

        // reconstruct 4 quadrants, transpose through sT, store
#pragma unroll 1
        for (int m = 0; m < 4; m++) {
            __syncthreads();
#pragma unroll
            for (int j = 0; j < 4; j++) {
#pragma unroll
                for (int p = 0; p < 2; p++) {
                    u64x S;
                    u64x Ps = add2(P0[j * 2 + p], P2[j * 2 + p]);
                    u64x Pd = sub2(P0[j * 2 + p], P2[j * 2 + p]);
                    if (m == 0)      S = add2(Ps, O[j * 2 + p]);
                    else if (m == 1) S = add2(Pd, R[j * 2 + p]);
                    else if (m == 2) S = sub2(Ps, O[j * 2 + p]);
                    else             S = sub2(Pd, R[j * 2 + p]);
                    float v0, v1;
                    unpack2(S, v0, v1);
                    int tl = warp * 4 + j;
                    int rbase = p * 64 + 2 * lane;
                    sT[rbase * 65 + tl]       = v0;
                    sT[(rbase + 1) * 65 + tl] = v1;
                }
            }
            __syncthreads();
            int tbase = m * 1024 + tq * 256 + pass * 64;
#pragma unroll
            for (int ii = 0; ii < 4; ii++) {
                int i = ii * 512 + tid;        // 2048 float4
                int rr = i >> 4, c4 = i & 15;
                const float* sp = sT + rr * 65 + c4 * 4;
                float4 vv = make_float4(sp[0], sp[1], sp[2], sp[3]);
                *(float4*)&out[(size_t)(r0 + rr) * NL + tbase + c4 * 4] = vv;
            }
        }
    }
}

// ================= launch =================
extern "C" void kernel_launch(void* const* d_in, const int* in_sizes, int n_in,
                              void* d_out, int out_size) {
    const float* q  = (const float*)d_in[0];
    const float* k  = (const float*)d_in[1];
    // d_in[2] = v, never used by the reference
    const float* w1 = (const float*)d_in[3];
    const float* w2 = (const float*)d_in[4];
    const int* iq   = (const int*)d_in[5];
    const int* ikv  = (const int*)d_in[6];
    float* out = (float*)d_out;

    cudaFuncSetAttribute(k1_forward, cudaFuncAttributeMaxDynamicSharedMemorySize, K1_SMEM);
    cudaFuncSetAttribute(k2a_attn,   cudaFuncAttributeMaxDynamicSharedMemorySize, K2A_SMEM);
    cudaFuncSetAttribute(k2b_wproj,  cudaFuncAttributeMaxDynamicSharedMemorySize, K2B_SMEM);
    cudaFuncSetAttribute(k3_inverse, cudaFuncAttributeMaxDynamicSharedMemorySize, K3_SMEM);

    k0_init<<<16, 256>>>();
    k1_forward<<<dim3(4, NB, 8), 256, K1_SMEM>>>(q, k, iq, ikv);
    k2a_attn<<<dim3(NB * NH, 2), 256, K2A_SMEM>>>();
    k2b_wproj<<<dim3(NH, 16), 256, K2B_SMEM>>>(w1, w2, iq);
    k3_inverse<<<dim3(32, 4), 512, K3_SMEM>>>(out, iq);
}

// round 13
// speedup vs baseline: 1.8317x; 1.3670x over previous
#include <cuda_runtime.h>
#include <math.h>

#define NB 8
#define NL 4096
#define NH 8
#define NM 64
#define NCH 512

typedef unsigned long long u64x;

__device__ ulonglong2 g_ts[4096];
__device__ float2 g_F[8 * NB * NM * NCH];
__device__ float2 g_C[NB * NH * 64 * 64];
__device__ float2 g_O[NB * NH * 64 * NM];

static __device__ __forceinline__ u64x fma2(u64x a, u64x b, u64x c) {
    u64x d; asm("fma.rn.f32x2 %0,%1,%2,%3;" : "=l"(d) : "l"(a), "l"(b), "l"(c)); return d;
}
static __device__ __forceinline__ u64x add2(u64x a, u64x b) {
    u64x d; asm("add.rn.f32x2 %0,%1,%2;" : "=l"(d) : "l"(a), "l"(b)); return d;
}
#define NEG1X2 0xBF800000BF800000ULL
#define KK2    0x3F3504F33F3504F3ULL
#define NKK2   0xBF3504F3BF3504F3ULL
static __device__ __forceinline__ u64x sub2(u64x a, u64x b) { return fma2(b, NEG1X2, a); }
static __device__ __forceinline__ u64x neg2(u64x a) { return fma2(a, NEG1X2, 0ULL); }
static __device__ __forceinline__ void unpack2(u64x d, float& lo, float& hi) {
    asm("mov.b64 {%0,%1},%2;" : "=f"(lo), "=f"(hi) : "l"(d));
}
static __device__ __forceinline__ u64x dup2(float v) {
    u64x d; asm("mov.b64 %0,{%1,%1};" : "=l"(d) : "f"(v)); return d;
}
static __device__ __forceinline__ u64x ldg64(const float* p) {
    u64x v; asm("ld.global.nc.u64 %0,[%1];" : "=l"(v) : "l"(p)); return v;
}

__global__ void k0_init() {
    int i = blockIdx.x * 256 + threadIdx.x;
    if (i < 4096) {
        float s, c;
        sincospif((float)i / 2048.0f, &s, &c);
        g_ts[i] = make_ulonglong2(dup2(c), dup2(s));
    }
}

// 8-pt real-input DFT: F0,F4 real; F1..F3 complex (F5..7 = conj)
static __device__ __forceinline__ void dft8(const u64x e[8],
    u64x& F0, u64x& F4, u64x& F1r, u64x& F1i, u64x& F2r, u64x& F2i, u64x& F3r, u64x& F3i)
{
    u64x e04 = add2(e[0], e[4]), d04 = sub2(e[0], e[4]);
    u64x e26 = add2(e[2], e[6]), d62 = sub2(e[6], e[2]);
    u64x e15 = add2(e[1], e[5]), s1 = sub2(e[1], e[5]);
    u64x e37 = add2(e[3], e[7]), s2 = sub2(e[3], e[7]);
    u64x t1 = sub2(s1, s2), t2 = add2(s1, s2);
    u64x S = add2(e04, e26), T = add2(e15, e37);
    F0 = add2(S, T); F4 = sub2(S, T);
    F2r = sub2(e04, e26); F2i = sub2(e37, e15);
    F1r = fma2(t1, KK2, d04);  F1i = fma2(t2, NKK2, d62);
    F3r = fma2(t1, NKK2, d04); F3i = neg2(fma2(t2, KK2, d62));
}

// ================= K1: forward sparse DFT, radix-16 staged butterfly =================
// u_j(t') = sum_{m<16} x[t'+256m] e^{-2pi i j m/16}, j=f&15; X[f] = sum_{t'<256} u_j e^{-2pi i f t'/4096}
// Slot planes: 0:u0r 1:u8r, then for j=1..7: 2j:ujr, 2j+1:uji.  u_{16-j} = conj(u_j).
// accR=Re, accS=-Im: accR += Pr*cc + Pi*ss ; accS += Pr*ss - Pi*cc.
#define K1_SMEM (4096 * 16 + 16 * 4 * 128 * 4 + 64)
__global__ void __launch_bounds__(256, 2) k1_forward(const float* __restrict__ qp,
                                                     const float* __restrict__ kp,
                                                     const int* __restrict__ iq,
                                                     const int* __restrict__ ikv) {
    extern __shared__ char sm[];
    ulonglong2* ts2 = (ulonglong2*)sm;
    float* xs = (float*)(ts2 + 4096);            // [16 slot][4 t'][128 ch] = 32KB
    u64x* xsw = (u64x*)xs;
    const ulonglong2* xs2 = (const ulonglong2*)xs;

    const int ctile = blockIdx.x, b = blockIdx.y;
    const int tensor = blockIdx.z >> 2, tq = blockIdx.z & 3;
    const float* src = tensor ? kp : qp;
    const int* idxarr = tensor ? ikv : iq;
    const int tid = threadIdx.x, lane = tid & 31, warp = tid >> 5;
    const unsigned FULL = 0xffffffffu;

    for (int i = tid; i < 4096; i += 256) ts2[i] = g_ts[i];

    const u64x C8 = dup2(0.92387953251128674f);
    const u64x S8 = dup2(0.38268343236508977f);

    // bucket 64 modes by pair-class key; warp w gets bucketed positions [8w, 8w+8)
    int Flo = idxarr[lane], Fhi = idxarr[lane + 32];
    int jlo = Flo & 15, jhi = Fhi & 15;
    int plo = (jlo == 0 || jlo == 8) ? 0 : ((jlo < 16 - jlo) ? jlo : 16 - jlo);
    int phi = (jhi == 0 || jhi == 8) ? 0 : ((jhi < 16 - jhi) ? jhi : 16 - jhi);
    int keylo = plo * 2 + (jlo >= 8);
    int keyhi = phi * 2 + (jhi >= 8);
    unsigned lm = (1u << lane) - 1u;
    int p_lo = 0, p_hi = 0, run = 0;
#pragma unroll
    for (int c = 0; c < 16; c++) {
        unsigned blo = __ballot_sync(FULL, keylo == c);
        unsigned bhi = __ballot_sync(FULL, keyhi == c);
        if (keylo == c) p_lo = run + __popc(blo & lm);
        if (keyhi == c) p_hi = run + __popc(blo) + __popc(bhi & lm);
        run += __popc(blo) + __popc(bhi);
    }
    int F[8], mi[8];
#pragma unroll
    for (int k = 0; k < 8; k++) {
        int tpos = warp * 8 + k;
        unsigned ba = __ballot_sync(FULL, p_lo == tpos);
        unsigned bb = __ballot_sync(FULL, p_hi == tpos);
        int m = ba ? (__ffs(ba) - 1) : (32 + __ffs(bb) - 1);
        mi[k] = m;
        F[k] = __shfl_sync(FULL, (m < 32) ? Flo : Fhi, m & 31);
    }
    bool uni = true;
#pragma unroll
    for (int k = 0; k < 8; k++) {
        int jexp = (k < 4) ? ((warp == 0) ? 0 : warp) : ((warp == 0) ? 8 : 16 - warp);
        uni = uni && ((F[k] & 15) == jexp);
    }

    u64x accR[16], accS[16]; int idx[8];
#pragma unroll
    for (int k = 0; k < 16; k++) { accR[k] = 0; accS[k] = 0; }

    const float* base = src + (size_t)b * NL * NCH + ctile * 128;
    const int stt = tid >> 6, sduo = tid & 63;   // staging: t' 0..3, ch-pair 0..63

    for (int cc = 0; cc < 16; cc++) {
        const int tp0 = tq * 64 + cc * 4;
        __syncthreads();
        {
            const float* gp = base + (size_t)(tp0 + stt) * NCH + sduo * 2;
            u64x a[16];
#pragma unroll
            for (int m = 0; m < 16; m++) a[m] = ldg64(gp + (size_t)m * 256 * NCH);
            u64x ev[8], od[8];
#pragma unroll
            for (int r = 0; r < 8; r++) { ev[r] = a[2 * r]; od[r] = a[2 * r + 1]; }
            u64x E0, E4, E1r, E1i, E2r, E2i, E3r, E3i;
            u64x O0, O4, O1r, O1i, O2r, O2i, O3r, O3i;
            dft8(ev, E0, E4, E1r, E1i, E2r, E2i, E3r, E3i);
            dft8(od, O0, O4, O1r, O1i, O2r, O2i, O3r, O3i);
            u64x o[16];
            o[0] = add2(E0, O0);
            o[1] = sub2(E0, O0);
            o[2] = fma2(O1r, C8, fma2(O1i, S8, E1r));
            o[3] = fma2(O1i, C8, fma2(neg2(O1r), S8, E1i));
            o[4] = fma2(add2(O2r, O2i), KK2, E2r);
            o[5] = fma2(sub2(O2i, O2r), KK2, E2i);
            o[6] = fma2(O3r, S8, fma2(O3i, C8, E3r));
            o[7] = fma2(O3i, S8, fma2(neg2(O3r), C8, E3i));
            o[8] = E4;
            o[9] = neg2(O4);
            o[10] = sub2(add2(E3r, E3r), o[6]);  o[11] = sub2(o[7], add2(E3i, E3i));
            o[12] = sub2(add2(E2r, E2r), o[4]);  o[13] = sub2(o[5], add2(E2i, E2i));
            o[14] = sub2(add2(E1r, E1r), o[2]);  o[15] = sub2(o[3], add2(E1i, E1i));
#pragma unroll
            for (int s = 0; s < 16; s++) xsw[(s * 4 + stt) * 64 + sduo] = o[s];
        }
        __syncthreads();
#pragma unroll
        for (int k = 0; k < 8; k++) idx[k] = (F[k] * tp0) & 4095;

        if (uni && warp > 0) {
            const int pRE = 2 * warp, pIM = 2 * warp + 1;
#pragma unroll
            for (int tt = 0; tt < 4; tt++) {
                ulonglong2 RE = xs2[(pRE * 4 + tt) * 32 + lane];
                ulonglong2 IM = xs2[(pIM * 4 + tt) * 32 + lane];
                u64x nIMx = neg2(IM.x), nIMy = neg2(IM.y);
#pragma unroll
                for (int k = 0; k < 8; k++) {
                    ulonglong2 cs = ts2[idx[k]];
                    u64x pix = (k < 4) ? IM.x : nIMx, npix = (k < 4) ? nIMx : IM.x;
                    u64x piy = (k < 4) ? IM.y : nIMy, npiy = (k < 4) ? nIMy : IM.y;
                    accR[k * 2 + 0] = fma2(RE.x, cs.x, accR[k * 2 + 0]);
                    accR[k * 2 + 0] = fma2(pix,  cs.y, accR[k * 2 + 0]);
                    accS[k * 2 + 0] = fma2(RE.x, cs.y, accS[k * 2 + 0]);
                    accS[k * 2 + 0] = fma2(npix, cs.x, accS[k * 2 + 0]);
                    accR[k * 2 + 1] = fma2(RE.y, cs.x, accR[k * 2 + 1]);
                    accR[k * 2 + 1] = fma2(piy,  cs.y, accR[k * 2 + 1]);
                    accS[k * 2 + 1] = fma2(RE.y, cs.y, accS[k * 2 + 1]);
                    accS[k * 2 + 1] = fma2(npiy, cs.x, accS[k * 2 + 1]);
                    idx[k] = (idx[k] + F[k]) & 4095;
                }
            }
        } else if (uni) {
#pragma unroll
            for (int tt = 0; tt < 4; tt++) {
                ulonglong2 R0 = xs2[(0 * 4 + tt) * 32 + lane];
                ulonglong2 R8 = xs2[(1 * 4 + tt) * 32 + lane];
#pragma unroll
                for (int k = 0; k < 8; k++) {
                    ulonglong2 cs = ts2[idx[k]];
                    u64x prx = (k < 4) ? R0.x : R8.x;
                    u64x pry = (k < 4) ? R0.y : R8.y;
                    accR[k * 2 + 0] = fma2(prx, cs.x, accR[k * 2 + 0]);
                    accS[k * 2 + 0] = fma2(prx, cs.y, accS[k * 2 + 0]);
                    accR[k * 2 + 1] = fma2(pry, cs.x, accR[k * 2 + 1]);
                    accS[k * 2 + 1] = fma2(pry, cs.y, accS[k * 2 + 1]);
                    idx[k] = (idx[k] + F[k]) & 4095;
                }
            }
        } else {
            // generic fallback: per-mode plane resolution
            for (int tt = 0; tt < 4; tt++) {
#pragma unroll
                for (int k = 0; k < 8; k++) {
                    int j = F[k] & 15;
                    int jj = (j > 8) ? (16 - j) : j;
                    bool realu = (j == 0) || (j == 8);
                    int sR = (j == 0) ? 0 : ((j == 8) ? 1 : 2 * jj);
                    ulonglong2 RE = xs2[(sR * 4 + tt) * 32 + lane];
                    u64x pix = 0, piy = 0;
                    if (!realu) {
                        ulonglong2 IM = xs2[((2 * jj + 1) * 4 + tt) * 32 + lane];
                        pix = (j > 8) ? neg2(IM.x) : IM.x;
                        piy = (j > 8) ? neg2(IM.y) : IM.y;
                    }
                    ulonglong2 cs = ts2[idx[k]];
                    accR[k * 2 + 0] = fma2(RE.x, cs.x, accR[k * 2 + 0]);
                    accR[k * 2 + 0] = fma2(pix,  cs.y, accR[k * 2 + 0]);
                    accS[k * 2 + 0] = fma2(RE.x, cs.y, accS[k * 2 + 0]);
                    accS[k * 2 + 0] = fma2(neg2(pix), cs.x, accS[k * 2 + 0]);
                    accR[k * 2 + 1] = fma2(RE.y, cs.x, accR[k * 2 + 1]);
                    accR[k * 2 + 1] = fma2(piy,  cs.y, accR[k * 2 + 1]);
                    accS[k * 2 + 1] = fma2(RE.y, cs.y, accS[k * 2 + 1]);
                    accS[k * 2 + 1] = fma2(neg2(piy), cs.x, accS[k * 2 + 1]);
                    idx[k] = (idx[k] + F[k]) & 4095;
                }
            }
        }
    }

    const int ch = ctile * 128 + lane * 4;
    float2* dst = g_F + ((size_t)((tq * 2 + tensor) * NB + b) * NM) * NCH;
#pragma unroll
    for (int k = 0; k < 8; k++) {
        float r0, r1, r2, r3, s0, s1, s2, s3;
        unpack2(accR[k * 2 + 0], r0, r1);
        unpack2(accS[k * 2 + 0], s0, s1);
        unpack2(accR[k * 2 + 1], r2, r3);
        unpack2(accS[k * 2 + 1], s2, s3);
        float2* dp = &dst[(size_t)mi[k] * NCH + ch];
        *(float4*)(dp)     = make_float4(r0, -s0, r1, -s1);
        *(float4*)(dp + 2) = make_float4(r2, -s2, r3, -s3);
    }
}

// ================= K2a: per-(b,h,xhalf) tanh attention, writes C =================
#define K2A_SMEM (32 * 64 * 8 + 64 * 65 * 8 + 64 * 33 * 8)
__global__ void __launch_bounds__(256, 3) k2a_attn() {
    extern __shared__ char sm[];
    float2* sFq  = (float2*)sm;
    float2* sFkT = sFq + 32 * 64;
    float2* sA   = sFkT + 64 * 65;

    const int bh = blockIdx.x, b = bh >> 3, h = bh & 7;
    const int x0 = blockIdx.y * 32;
    const int tid = threadIdx.x;
    const size_t QSTR = (size_t)2 * NB * NM * NCH;

    for (int i = tid; i < 2048; i += 256) {
        int xl = i >> 6, e = i & 63;
        size_t o0 = ((size_t)(b) * NM + (x0 + xl)) * NCH + h * 64 + e;
        float2 a0 = g_F[o0], a1 = g_F[o0 + QSTR], a2 = g_F[o0 + 2 * QSTR], a3 = g_F[o0 + 3 * QSTR];
        sFq[xl * 64 + e] = make_float2(a0.x + a1.x + a2.x + a3.x, a0.y + a1.y + a2.y + a3.y);
    }
    for (int i = tid; i < 4096; i += 256) {
        int e = i & 63, f = i >> 6;
        size_t o0 = ((size_t)(NB + b) * NM + f) * NCH + h * 64 + e;
        float2 a0 = g_F[o0], a1 = g_F[o0 + QSTR], a2 = g_F[o0 + 2 * QSTR], a3 = g_F[o0 + 3 * QSTR];
        sFkT[e * 65 + f] = make_float2(a0.x + a1.x + a2.x + a3.x, a0.y + a1.y + a2.y + a3.y);
    }
    __syncthreads();

#pragma unroll 1
    for (int p = 0; p < 8; p++) {
        int i = p * 256 + tid, xl = i >> 6, y = i & 63;
        float re = 0.f, im = 0.f;
#pragma unroll 4
        for (int e = 0; e < 64; e++) {
            float2 a = sFq[xl * 64 + e];
            float2 c = sFkT[e * 65 + y];
            re += a.x * c.x - a.y * c.y;
            im += a.x * c.y + a.y * c.x;
        }
        sA[y * 33 + xl] = make_float2(tanhf(re), tanhf(im));
    }
    __syncthreads();

#pragma unroll 1
    for (int p = 0; p < 8; p++) {
        int i = p * 256 + tid, xl = i & 31, e = i >> 5;
        float re = 0.f, im = 0.f;
#pragma unroll 4
        for (int y = 0; y < 64; y++) {
            float2 a  = sA[y * 33 + xl];
            float2 kv = sFkT[e * 65 + y];
            re += a.x * kv.x - a.y * kv.y;
            im += a.x * kv.y + a.y * kv.x;
        }
        g_C[((size_t)(h * 8 + b) * 64 + e) * 64 + x0 + xl] = make_float2(re, im);
    }
}

// ================= K2b: weight contraction, w read exactly once =================
#define K2B_SMEM (8 * 64 * 4 * 8)
__global__ void __launch_bounds__(256, 4) k2b_wproj(const float* __restrict__ w1,
                                                    const float* __restrict__ w2,
                                                    const int* __restrict__ iq) {
    extern __shared__ char sm[];
    float2* sC = (float2*)sm;

    const int h = blockIdx.x, x0 = blockIdx.y * 4;
    const int tid = threadIdx.x;

    for (int i = tid; i < 2048; i += 256) {
        int xl = i & 3, e = (i >> 2) & 63, b = i >> 8;
        sC[(b * 64 + e) * 4 + xl] = g_C[((size_t)(h * 8 + b) * 64 + e) * 64 + x0 + xl];
    }
    __syncthreads();

    const int xl = tid & 3, x = x0 + xl, o = tid >> 2;
    float accR[8], accI[8];
#pragma unroll
    for (int b = 0; b < 8; b++) { accR[b] = 0.f; accI[b] = 0.f; }

    size_t wbase = (((size_t)h * 64) * 64 + o) * 64 + x;
#pragma unroll 4
    for (int e = 0; e < 64; e++) {
        float wr = w1[wbase + (size_t)e * 4096];
        float wi = w2[wbase + (size_t)e * 4096];
#pragma unroll
        for (int b = 0; b < 8; b++) {
            float2 c = sC[(b * 64 + e) * 4 + xl];
            accR[b] += c.x * wr - c.y * wi;
            accI[b] += c.x * wi + c.y * wr;
        }
    }

    int fx = iq[x];
    float s = ((fx == 0) || (fx == NL / 2) ? 1.0f : 2.0f) * 9.313225746154785e-10f;
#pragma unroll
    for (int b = 0; b < 8; b++) {
        int row = (b * 8 + h) * 64 + o;
        g_O[(size_t)row * NM + x] = make_float2(s * accR[b], -s * accI[b]);
    }
}

// ================= K3: inverse sparse DFT (radix-4, 128 rows/CTA, 4 rows/lane) =================
#define K3_SMEM (4096 * 16 + 32768 + 32768 + 128 * 65 * 4 + 64 * 8 + 64)
__global__ void __launch_bounds__(512, 1) k3_inverse(float* __restrict__ out,
                                                     const int* __restrict__ iq) {
    extern __shared__ char sm[];
    ulonglong2* ts2 = (ulonglong2*)sm;
    float* sA = (float*)(ts2 + 4096);
    float* sB = sA + 64 * 128;
    float* sT = sB + 64 * 128;
    int2* sperm = (int2*)(sT + 128 * 65);
    int* soff = (int*)(sperm + 64);

    const int rt = blockIdx.x;
    const int tq = blockIdx.y;
    const int r0 = rt * 128;
    const int tid = threadIdx.x, lane = tid & 31, warp = tid >> 5;

    for (int i = tid; i < 4096; i += 512) ts2[i] = g_ts[i];
    for (int i = tid; i < 8192; i += 512) {
        int rr = i >> 6, f = i & 63;
        float2 v = g_O[(size_t)(r0 + rr) * NM + f];
        int half = rr >> 6, pr = (rr & 63) >> 1, sl = half * 2 + (rr & 1);
        sA[f * 128 + pr * 4 + sl] = v.x;
        sB[f * 128 + pr * 4 + sl] = v.y;
    }
    if (warp == 0) {
        const unsigned FULL = 0xffffffffu;
        int Flo = iq[lane], Fhi = iq[lane + 32];
        int clo = Flo & 3, chi = Fhi & 3;
        unsigned mlo[4], mhi[4];
        int off[5]; off[0] = 0;
#pragma unroll
        for (int c = 0; c < 4; c++) {
            mlo[c] = __ballot_sync(FULL, clo == c);
            mhi[c] = __ballot_sync(FULL, chi == c);
        }
#pragma unroll
        for (int c = 0; c < 4; c++) off[c + 1] = off[c] + __popc(mlo[c]) + __popc(mhi[c]);
        unsigned lmm = (1u << lane) - 1u;
        int p_lo = off[clo] + __popc(mlo[clo] & lmm);
        int p_hi = off[chi] + __popc(mlo[chi]) + __popc(mhi[chi] & lmm);
        sperm[p_lo] = make_int2(lane, Flo);
        sperm[p_hi] = make_int2(lane + 32, Fhi);
        if (lane < 5) soff[lane] = off[lane];
    }
    __syncthreads();

    const ulonglong2* sAd = (const ulonglong2*)sA;
    const ulonglong2* sBd = (const ulonglong2*)sB;
    const int o0 = soff[0], o1 = soff[1], o2 = soff[2], o3 = soff[3], o4 = soff[4];

#pragma unroll 1
    for (int pass = 0; pass < 4; pass++) {
        const int t0 = tq * 256 + pass * 64 + warp * 4;
        u64x P0[8], P2[8], O[8], R[8];
#pragma unroll
        for (int j = 0; j < 8; j++) { P0[j] = 0; P2[j] = 0; O[j] = 0; R[j] = 0; }

#pragma unroll 2
        for (int pos = o0; pos < o1; pos++) {
            int2 pf = sperm[pos];
            ulonglong2 A = sAd[pf.x * 32 + lane], B = sBd[pf.x * 32 + lane];
            int id = (pf.y * t0) & 4095;
#pragma unroll
            for (int j = 0; j < 4; j++) {
                ulonglong2 cs = ts2[id];
                P0[j * 2 + 0] = fma2(A.x, cs.x, P0[j * 2 + 0]);  P0[j * 2 + 0] = fma2(B.x, cs.y, P0[j * 2 + 0]);
                P0[j * 2 + 1] = fma2(A.y, cs.x, P0[j * 2 + 1]);  P0[j * 2 + 1] = fma2(B.y, cs.y, P0[j * 2 + 1]);
                id = (id + pf.y) & 4095;
            }
        }
#pragma unroll 2
        for (int pos = o1; pos < o2; pos++) {
            int2 pf = sperm[pos];
            ulonglong2 A = sAd[pf.x * 32 + lane], B = sBd[pf.x * 32 + lane];
            u64x nAx = neg2(A.x), nAy = neg2(A.y);
            int id = (pf.y * t0) & 4095;
#pragma unroll
            for (int j = 0; j < 4; j++) {
                ulonglong2 cs = ts2[id];
                O[j * 2 + 0] = fma2(A.x, cs.x, O[j * 2 + 0]);   O[j * 2 + 0] = fma2(B.x, cs.y, O[j * 2 + 0]);
                O[j * 2 + 1] = fma2(A.y, cs.x, O[j * 2 + 1]);   O[j * 2 + 1] = fma2(B.y, cs.y, O[j * 2 + 1]);
                R[j * 2 + 0] = fma2(B.x, cs.x, R[j * 2 + 0]);   R[j * 2 + 0] = fma2(nAx, cs.y, R[j * 2 + 0]);
                R[j * 2 + 1] = fma2(B.y, cs.x, R[j * 2 + 1]);   R[j * 2 + 1] = fma2(nAy, cs.y, R[j * 2 + 1]);
                id = (id + pf.y) & 4095;
            }
        }
#pragma unroll 2
        for (int pos = o2; pos < o3; pos++) {
            int2 pf = sperm[pos];
            ulonglong2 A = sAd[pf.x * 32 + lane], B = sBd[pf.x * 32 + lane];
            int id = (pf.y * t0) & 4095;
#pragma unroll
            for (int j = 0; j < 4; j++) {
                ulonglong2 cs = ts2[id];
                P2[j * 2 + 0] = fma2(A.x, cs.x, P2[j * 2 + 0]);  P2[j * 2 + 0] = fma2(B.x, cs.y, P2[j * 2 + 0]);
                P2[j * 2 + 1] = fma2(A.y, cs.x, P2[j * 2 + 1]);  P2[j * 2 + 1] = fma2(B.y, cs.y, P2[j * 2 + 1]);
                id = (id + pf.y) & 4095;
            }
        }
#pragma unroll 2
        for (int pos = o3; pos < o4; pos++) {
            int2 pf = sperm[pos];
            ulonglong2 A = sAd[pf.x * 32 + lane], B = sBd[pf.x * 32 + lane];
            u64x nBx = neg2(B.x), nBy = neg2(B.y);
            int id = (pf.y * t0) & 4095;
#pragma unroll
            for (int j = 0; j < 4; j++) {
                ulonglong2 cs = ts2[id];
                O[j * 2 + 0] = fma2(A.x, cs.x, O[j * 2 + 0]);   O[j * 2 + 0] = fma2(B.x, cs.y, O[j * 2 + 0]);
                O[j * 2 + 1] = fma2(A.y, cs.x, O[j * 2 + 1]);   O[j * 2 + 1] = fma2(B.y, cs.y, O[j * 2 + 1]);
                R[j * 2 + 0] = fma2(nBx, cs.x, R[j * 2 + 0]);   R[j * 2 + 0] = fma2(A.x, cs.y, R[j * 2 + 0]);
                R[j * 2 + 1] = fma2(nBy, cs.x, R[j * 2 + 1]);   R[j * 2 + 1] = fma2(A.y, cs.y, R[j * 2 + 1]);
                id = (id + pf.y) & 4095;
            }
        }

#pragma unroll 1
        for (int m = 0; m < 4; m++) {
            __syncthreads();
#pragma unroll
            for (int j = 0; j < 4; j++) {
#pragma unroll
                for (int p = 0; p < 2; p++) {
                    u64x S;
                    u64x Ps = add2(P0[j * 2 + p], P2[j * 2 + p]);
                    u64x Pd = sub2(P0[j * 2 + p], P2[j * 2 + p]);
                    if (m == 0)      S = add2(Ps, O[j * 2 + p]);
                    else if (m == 1) S = add2(Pd, R[j * 2 + p]);
                    else if (m == 2) S = sub2(Ps, O[j * 2 + p]);
                    else             S = sub2(Pd, R[j * 2 + p]);
                    float v0, v1;
                    unpack2(S, v0, v1);
                    int tl = warp * 4 + j;
                    int rbase = p * 64 + 2 * lane;
                    sT[rbase * 65 + tl]       = v0;
                    sT[(rbase + 1) * 65 + tl] = v1;
                }
            }
            __syncthreads();
            int tbase = m * 1024 + tq * 256 + pass * 64;
#pragma unroll
            for (int ii = 0; ii < 4; ii++) {
                int i = ii * 512 + tid;
                int rr = i >> 4, c4 = i & 15;
                const float* sp = sT + rr * 65 + c4 * 4;
                float4 vv = make_float4(sp[0], sp[1], sp[2], sp[3]);
                *(float4*)&out[(size_t)(r0 + rr) * NL + tbase + c4 * 4] = vv;
            }
        }
    }
}

// ================= launch =================
extern "C" void kernel_launch(void* const* d_in, const int* in_sizes, int n_in,
                              void* d_out, int out_size) {
    const float* q  = (const float*)d_in[0];
    const float* k  = (const float*)d_in[1];
    const float* w1 = (const float*)d_in[3];
    const float* w2 = (const float*)d_in[4];
    const int* iq   = (const int*)d_in[5];
    const int* ikv  = (const int*)d_in[6];
    float* out = (float*)d_out;

    cudaFuncSetAttribute(k1_forward, cudaFuncAttributeMaxDynamicSharedMemorySize, K1_SMEM);
    cudaFuncSetAttribute(k2a_attn,   cudaFuncAttributeMaxDynamicSharedMemorySize, K2A_SMEM);
    cudaFuncSetAttribute(k2b_wproj,  cudaFuncAttributeMaxDynamicSharedMemorySize, K2B_SMEM);
    cudaFuncSetAttribute(k3_inverse, cudaFuncAttributeMaxDynamicSharedMemorySize, K3_SMEM);

    k0_init<<<16, 256>>>();
    k1_forward<<<dim3(4, NB, 8), 256, K1_SMEM>>>(q, k, iq, ikv);
    k2a_attn<<<dim3(NB * NH, 2), 256, K2A_SMEM>>>();
    k2b_wproj<<<dim3(NH, 16), 256, K2B_SMEM>>>(w1, w2, iq);
    k3_inverse<<<dim3(32, 4), 512, K3_SMEM>>>(out, iq);
}

// round 15
// speedup vs baseline: 2.0444x; 1.1161x over previous
#include <cuda_runtime.h>
#include <math.h>

#define NB 8
#define NL 4096
#define NH 8
#define NM 64
#define NCH 512

typedef unsigned long long u64x;

__device__ ulonglong2 g_ts[4096];
__device__ float2 g_F[8 * NB * NM * NCH];
__device__ float2 g_C[NB * NH * 64 * 64];
__device__ float2 g_O[NB * NH * 64 * NM];

static __device__ __forceinline__ u64x fma2(u64x a, u64x b, u64x c) {
    u64x d; asm("fma.rn.f32x2 %0,%1,%2,%3;" : "=l"(d) : "l"(a), "l"(b), "l"(c)); return d;
}
static __device__ __forceinline__ u64x add2(u64x a, u64x b) {
    u64x d; asm("add.rn.f32x2 %0,%1,%2;" : "=l"(d) : "l"(a), "l"(b)); return d;
}
#define NEG1X2 0xBF800000BF800000ULL
#define KK2    0x3F3504F33F3504F3ULL
#define NKK2   0xBF3504F3BF3504F3ULL
static __device__ __forceinline__ u64x sub2(u64x a, u64x b) { return fma2(b, NEG1X2, a); }
static __device__ __forceinline__ u64x neg2(u64x a) { return fma2(a, NEG1X2, 0ULL); }
static __device__ __forceinline__ void unpack2(u64x d, float& lo, float& hi) {
    asm("mov.b64 {%0,%1},%2;" : "=f"(lo), "=f"(hi) : "l"(d));
}
static __device__ __forceinline__ u64x dup2(float v) {
    u64x d; asm("mov.b64 %0,{%1,%1};" : "=l"(d) : "f"(v)); return d;
}
static __device__ __forceinline__ u64x ldg64(const float* p) {
    u64x v; asm("ld.global.nc.u64 %0,[%1];" : "=l"(v) : "l"(p)); return v;
}

__global__ void k0_init() {
    int i = blockIdx.x * 256 + threadIdx.x;
    if (i < 4096) {
        float s, c;
        sincospif((float)i / 2048.0f, &s, &c);
        g_ts[i] = make_ulonglong2(dup2(c), dup2(s));
    }
}

// 8-pt real-input DFT: F0,F4 real; F1..F3 complex (F5..7 = conj)
static __device__ __forceinline__ void dft8(const u64x e[8],
    u64x& F0, u64x& F4, u64x& F1r, u64x& F1i, u64x& F2r, u64x& F2i, u64x& F3r, u64x& F3i)
{
    u64x e04 = add2(e[0], e[4]), d04 = sub2(e[0], e[4]);
    u64x e26 = add2(e[2], e[6]), d62 = sub2(e[6], e[2]);
    u64x e15 = add2(e[1], e[5]), s1 = sub2(e[1], e[5]);
    u64x e37 = add2(e[3], e[7]), s2 = sub2(e[3], e[7]);
    u64x t1 = sub2(s1, s2), t2 = add2(s1, s2);
    u64x S = add2(e04, e26), T = add2(e15, e37);
    F0 = add2(S, T); F4 = sub2(S, T);
    F2r = sub2(e04, e26); F2i = sub2(e37, e15);
    F1r = fma2(t1, KK2, d04);  F1i = fma2(t2, NKK2, d62);
    F3r = fma2(t1, NKK2, d04); F3i = neg2(fma2(t2, KK2, d62));
}

// ================= K1: forward sparse DFT, radix-16 staged butterfly =================
#define K1_SMEM (4096 * 16 + 16 * 4 * 128 * 4 + 64)
__global__ void __launch_bounds__(256, 2) k1_forward(const float* __restrict__ qp,
                                                     const float* __restrict__ kp,
                                                     const int* __restrict__ iq,
                                                     const int* __restrict__ ikv) {
    extern __shared__ char sm[];
    ulonglong2* ts2 = (ulonglong2*)sm;
    float* xs = (float*)(ts2 + 4096);            // [16 slot][4 t'][128 ch]
    u64x* xsw = (u64x*)xs;
    const ulonglong2* xs2 = (const ulonglong2*)xs;

    const int ctile = blockIdx.x, b = blockIdx.y;
    const int tensor = blockIdx.z >> 2, tq = blockIdx.z & 3;
    const float* src = tensor ? kp : qp;
    const int* idxarr = tensor ? ikv : iq;
    const int tid = threadIdx.x, lane = tid & 31, warp = tid >> 5;
    const unsigned FULL = 0xffffffffu;

    for (int i = tid; i < 4096; i += 256) ts2[i] = g_ts[i];

    const u64x C8 = dup2(0.92387953251128674f);
    const u64x S8 = dup2(0.38268343236508977f);

    int Flo = idxarr[lane], Fhi = idxarr[lane + 32];
    int jlo = Flo & 15, jhi = Fhi & 15;
    int plo = (jlo == 0 || jlo == 8) ? 0 : ((jlo < 16 - jlo) ? jlo : 16 - jlo);
    int phi = (jhi == 0 || jhi == 8) ? 0 : ((jhi < 16 - jhi) ? jhi : 16 - jhi);
    int keylo = plo * 2 + (jlo >= 8);
    int keyhi = phi * 2 + (jhi >= 8);
    unsigned lm = (1u << lane) - 1u;
    int p_lo = 0, p_hi = 0, run = 0;
#pragma unroll
    for (int c = 0; c < 16; c++) {
        unsigned blo = __ballot_sync(FULL, keylo == c);
        unsigned bhi = __ballot_sync(FULL, keyhi == c);
        if (keylo == c) p_lo = run + __popc(blo & lm);
        if (keyhi == c) p_hi = run + __popc(blo) + __popc(bhi & lm);
        run += __popc(blo) + __popc(bhi);
    }
    int F[8], mi[8];
#pragma unroll
    for (int k = 0; k < 8; k++) {
        int tpos = warp * 8 + k;
        unsigned ba = __ballot_sync(FULL, p_lo == tpos);
        unsigned bb = __ballot_sync(FULL, p_hi == tpos);
        int m = ba ? (__ffs(ba) - 1) : (32 + __ffs(bb) - 1);
        mi[k] = m;
        F[k] = __shfl_sync(FULL, (m < 32) ? Flo : Fhi, m & 31);
    }
    bool uni = true;
#pragma unroll
    for (int k = 0; k < 8; k++) {
        int jexp = (k < 4) ? ((warp == 0) ? 0 : warp) : ((warp == 0) ? 8 : 16 - warp);
        uni = uni && ((F[k] & 15) == jexp);
    }

    u64x accR[16], accS[16]; int idx[8];
#pragma unroll
    for (int k = 0; k < 16; k++) { accR[k] = 0; accS[k] = 0; }

    const float* base = src + (size_t)b * NL * NCH + ctile * 128;
    const int stt = tid >> 6, sduo = tid & 63;

    for (int cc = 0; cc < 16; cc++) {
        const int tp0 = tq * 64 + cc * 4;
        __syncthreads();
        {
            const float* gp = base + (size_t)(tp0 + stt) * NCH + sduo * 2;
            u64x a[16];
#pragma unroll
            for (int m = 0; m < 16; m++) a[m] = ldg64(gp + (size_t)m * 256 * NCH);
            u64x ev[8], od[8];
#pragma unroll
            for (int r = 0; r < 8; r++) { ev[r] = a[2 * r]; od[r] = a[2 * r + 1]; }
            u64x E0, E4, E1r, E1i, E2r, E2i, E3r, E3i;
            u64x O0, O4, O1r, O1i, O2r, O2i, O3r, O3i;
            dft8(ev, E0, E4, E1r, E1i, E2r, E2i, E3r, E3i);
            dft8(od, O0, O4, O1r, O1i, O2r, O2i, O3r, O3i);
            u64x o[16];
            o[0] = add2(E0, O0);
            o[1] = sub2(E0, O0);
            o[2] = fma2(O1r, C8, fma2(O1i, S8, E1r));
            o[3] = fma2(O1i, C8, fma2(neg2(O1r), S8, E1i));
            o[4] = fma2(add2(O2r, O2i), KK2, E2r);
            o[5] = fma2(sub2(O2i, O2r), KK2, E2i);
            o[6] = fma2(O3r, S8, fma2(O3i, C8, E3r));
            o[7] = fma2(O3i, S8, fma2(neg2(O3r), C8, E3i));
            o[8] = E4;
            o[9] = neg2(O4);
            o[10] = sub2(add2(E3r, E3r), o[6]);  o[11] = sub2(o[7], add2(E3i, E3i));
            o[12] = sub2(add2(E2r, E2r), o[4]);  o[13] = sub2(o[5], add2(E2i, E2i));
            o[14] = sub2(add2(E1r, E1r), o[2]);  o[15] = sub2(o[3], add2(E1i, E1i));
#pragma unroll
            for (int s = 0; s < 16; s++) xsw[(s * 4 + stt) * 64 + sduo] = o[s];
        }
        __syncthreads();
#pragma unroll
        for (int k = 0; k < 8; k++) idx[k] = (F[k] * tp0) & 4095;

        if (uni && warp > 0) {
            const int pRE = 2 * warp, pIM = 2 * warp + 1;
#pragma unroll
            for (int tt = 0; tt < 4; tt++) {
                ulonglong2 RE = xs2[(pRE * 4 + tt) * 32 + lane];
                ulonglong2 IM = xs2[(pIM * 4 + tt) * 32 + lane];
                u64x nIMx = neg2(IM.x), nIMy = neg2(IM.y);
#pragma unroll
                for (int k = 0; k < 8; k++) {
                    ulonglong2 cs = ts2[idx[k]];
                    u64x pix = (k < 4) ? IM.x : nIMx, npix = (k < 4) ? nIMx : IM.x;
                    u64x piy = (k < 4) ? IM.y : nIMy, npiy = (k < 4) ? nIMy : IM.y;
                    accR[k * 2 + 0] = fma2(RE.x, cs.x, accR[k * 2 + 0]);
                    accR[k * 2 + 0] = fma2(pix,  cs.y, accR[k * 2 + 0]);
                    accS[k * 2 + 0] = fma2(RE.x, cs.y, accS[k * 2 + 0]);
                    accS[k * 2 + 0] = fma2(npix, cs.x, accS[k * 2 + 0]);
                    accR[k * 2 + 1] = fma2(RE.y, cs.x, accR[k * 2 + 1]);
                    accR[k * 2 + 1] = fma2(piy,  cs.y, accR[k * 2 + 1]);
                    accS[k * 2 + 1] = fma2(RE.y, cs.y, accS[k * 2 + 1]);
                    accS[k * 2 + 1] = fma2(npiy, cs.x, accS[k * 2 + 1]);
                    idx[k] = (idx[k] + F[k]) & 4095;
                }
            }
        } else if (uni) {
#pragma unroll
            for (int tt = 0; tt < 4; tt++) {
                ulonglong2 R0 = xs2[(0 * 4 + tt) * 32 + lane];
                ulonglong2 R8 = xs2[(1 * 4 + tt) * 32 + lane];
#pragma unroll
                for (int k = 0; k < 8; k++) {
                    ulonglong2 cs = ts2[idx[k]];
                    u64x prx = (k < 4) ? R0.x : R8.x;
                    u64x pry = (k < 4) ? R0.y : R8.y;
                    accR[k * 2 + 0] = fma2(prx, cs.x, accR[k * 2 + 0]);
                    accS[k * 2 + 0] = fma2(prx, cs.y, accS[k * 2 + 0]);
                    accR[k * 2 + 1] = fma2(pry, cs.x, accR[k * 2 + 1]);
                    accS[k * 2 + 1] = fma2(pry, cs.y, accS[k * 2 + 1]);
                    idx[k] = (idx[k] + F[k]) & 4095;
                }
            }
        } else {
            for (int tt = 0; tt < 4; tt++) {
#pragma unroll
                for (int k = 0; k < 8; k++) {
                    int j = F[k] & 15;
                    int jj = (j > 8) ? (16 - j) : j;
                    bool realu = (j == 0) || (j == 8);
                    int sR = (j == 0) ? 0 : ((j == 8) ? 1 : 2 * jj);
                    ulonglong2 RE = xs2[(sR * 4 + tt) * 32 + lane];
                    u64x pix = 0, piy = 0;
                    if (!realu) {
                        ulonglong2 IM = xs2[((2 * jj + 1) * 4 + tt) * 32 + lane];
                        pix = (j > 8) ? neg2(IM.x) : IM.x;
                        piy = (j > 8) ? neg2(IM.y) : IM.y;
                    }
                    ulonglong2 cs = ts2[idx[k]];
                    accR[k * 2 + 0] = fma2(RE.x, cs.x, accR[k * 2 + 0]);
                    accR[k * 2 + 0] = fma2(pix,  cs.y, accR[k * 2 + 0]);
                    accS[k * 2 + 0] = fma2(RE.x, cs.y, accS[k * 2 + 0]);
                    accS[k * 2 + 0] = fma2(neg2(pix), cs.x, accS[k * 2 + 0]);
                    accR[k * 2 + 1] = fma2(RE.y, cs.x, accR[k * 2 + 1]);
                    accR[k * 2 + 1] = fma2(piy,  cs.y, accR[k * 2 + 1]);
                    accS[k * 2 + 1] = fma2(RE.y, cs.y, accS[k * 2 + 1]);
                    accS[k * 2 + 1] = fma2(neg2(piy), cs.x, accS[k * 2 + 1]);
                    idx[k] = (idx[k] + F[k]) & 4095;
                }
            }
        }
    }

    const int ch = ctile * 128 + lane * 4;
    float2* dst = g_F + ((size_t)((tq * 2 + tensor) * NB + b) * NM) * NCH;
#pragma unroll
    for (int k = 0; k < 8; k++) {
        float r0, r1, r2, r3, s0, s1, s2, s3;
        unpack2(accR[k * 2 + 0], r0, r1);
        unpack2(accS[k * 2 + 0], s0, s1);
        unpack2(accR[k * 2 + 1], r2, r3);
        unpack2(accS[k * 2 + 1], s2, s3);
        float2* dp = &dst[(size_t)mi[k] * NCH + ch];
        *(float4*)(dp)     = make_float4(r0, -s0, r1, -s1);
        *(float4*)(dp + 2) = make_float4(r2, -s2, r3, -s3);
    }
}

// ================= K2a =================
#define K2A_SMEM (32 * 64 * 8 + 64 * 65 * 8 + 64 * 33 * 8)
__global__ void __launch_bounds__(256, 3) k2a_attn() {
    extern __shared__ char sm[];
    float2* sFq  = (float2*)sm;
    float2* sFkT = sFq + 32 * 64;
    float2* sA   = sFkT + 64 * 65;

    const int bh = blockIdx.x, b = bh >> 3, h = bh & 7;
    const int x0 = blockIdx.y * 32;
    const int tid = threadIdx.x;
    const size_t QSTR = (size_t)2 * NB * NM * NCH;

    for (int i = tid; i < 2048; i += 256) {
        int xl = i >> 6, e = i & 63;
        size_t o0 = ((size_t)(b) * NM + (x0 + xl)) * NCH + h * 64 + e;
        float2 a0 = g_F[o0], a1 = g_F[o0 + QSTR], a2 = g_F[o0 + 2 * QSTR], a3 = g_F[o0 + 3 * QSTR];
        sFq[xl * 64 + e] = make_float2(a0.x + a1.x + a2.x + a3.x, a0.y + a1.y + a2.y + a3.y);
    }
    for (int i = tid; i < 4096; i += 256) {
        int e = i & 63, f = i >> 6;
        size_t o0 = ((size_t)(NB + b) * NM + f) * NCH + h * 64 + e;
        float2 a0 = g_F[o0], a1 = g_F[o0 + QSTR], a2 = g_F[o0 + 2 * QSTR], a3 = g_F[o0 + 3 * QSTR];
        sFkT[e * 65 + f] = make_float2(a0.x + a1.x + a2.x + a3.x, a0.y + a1.y + a2.y + a3.y);
    }
    __syncthreads();

#pragma unroll 1
    for (int p = 0; p < 8; p++) {
        int i = p * 256 + tid, xl = i >> 6, y = i & 63;
        float re = 0.f, im = 0.f;
#pragma unroll 4
        for (int e = 0; e < 64; e++) {
            float2 a = sFq[xl * 64 + e];
            float2 c = sFkT[e * 65 + y];
            re += a.x * c.x - a.y * c.y;
            im += a.x * c.y + a.y * c.x;
        }
        sA[y * 33 + xl] = make_float2(tanhf(re), tanhf(im));
    }
    __syncthreads();

#pragma unroll 1
    for (int p = 0; p < 8; p++) {
        int i = p * 256 + tid, xl = i & 31, e = i >> 5;
        float re = 0.f, im = 0.f;
#pragma unroll 4
        for (int y = 0; y < 64; y++) {
            float2 a  = sA[y * 33 + xl];
            float2 kv = sFkT[e * 65 + y];
            re += a.x * kv.x - a.y * kv.y;
            im += a.x * kv.y + a.y * kv.x;
        }
        g_C[((size_t)(h * 8 + b) * 64 + e) * 64 + x0 + xl] = make_float2(re, im);
    }
}

// ================= K2b =================
#define K2B_SMEM (8 * 64 * 4 * 8)
__global__ void __launch_bounds__(256, 4) k2b_wproj(const float* __restrict__ w1,
                                                    const float* __restrict__ w2,
                                                    const int* __restrict__ iq) {
    extern __shared__ char sm[];
    float2* sC = (float2*)sm;

    const int h = blockIdx.x, x0 = blockIdx.y * 4;
    const int tid = threadIdx.x;

    for (int i = tid; i < 2048; i += 256) {
        int xl = i & 3, e = (i >> 2) & 63, b = i >> 8;
        sC[(b * 64 + e) * 4 + xl] = g_C[((size_t)(h * 8 + b) * 64 + e) * 64 + x0 + xl];
    }
    __syncthreads();

    const int xl = tid & 3, x = x0 + xl, o = tid >> 2;
    float accR[8], accI[8];
#pragma unroll
    for (int b = 0; b < 8; b++) { accR[b] = 0.f; accI[b] = 0.f; }

    size_t wbase = (((size_t)h * 64) * 64 + o) * 64 + x;
#pragma unroll 4
    for (int e = 0; e < 64; e++) {
        float wr = w1[wbase + (size_t)e * 4096];
        float wi = w2[wbase + (size_t)e * 4096];
#pragma unroll
        for (int b = 0; b < 8; b++) {
            float2 c = sC[(b * 64 + e) * 4 + xl];
            accR[b] += c.x * wr - c.y * wi;
            accI[b] += c.x * wi + c.y * wr;
        }
    }

    int fx = iq[x];
    float s = ((fx == 0) || (fx == NL / 2) ? 1.0f : 2.0f) * 9.313225746154785e-10f;
#pragma unroll
    for (int b = 0; b < 8; b++) {
        int row = (b * 8 + h) * 64 + o;
        g_O[(size_t)row * NM + x] = make_float2(s * accR[b], -s * accI[b]);
    }
}

// ================= K3: inverse sparse DFT (radix-8, conj-folded) =================
// out[t'+512m] = P0 + (-1)^m P4 + sum_j Vr_j cos(pi j m/4) - Vi_j sin(pi j m/4)
// W: Wr = A c + B s; code's Vi accumulates (A s - B c) direct, (B c - A s) folded.
static __device__ __forceinline__ void k3_seg_real(int lo, int hi, const int2* __restrict__ sperm,
    const ulonglong2* __restrict__ sAd, const ulonglong2* __restrict__ sBd,
    const ulonglong2* __restrict__ ts2, int lane, int t0, u64x P[4])
{
#pragma unroll 2
    for (int pos = lo; pos < hi; pos++) {
        int2 pf = sperm[pos];
        ulonglong2 A = sAd[pf.x * 32 + lane], B = sBd[pf.x * 32 + lane];
        int id = (pf.y * t0) & 4095;
#pragma unroll
        for (int j = 0; j < 2; j++) {
            ulonglong2 cs = ts2[id];
            P[j * 2 + 0] = fma2(A.x, cs.x, P[j * 2 + 0]);  P[j * 2 + 0] = fma2(B.x, cs.y, P[j * 2 + 0]);
            P[j * 2 + 1] = fma2(A.y, cs.x, P[j * 2 + 1]);  P[j * 2 + 1] = fma2(B.y, cs.y, P[j * 2 + 1]);
            id = (id + pf.y) & 4095;
        }
    }
}
template<bool FOLD>
static __device__ __forceinline__ void k3_seg_cplx(int lo, int hi, const int2* __restrict__ sperm,
    const ulonglong2* __restrict__ sAd, const ulonglong2* __restrict__ sBd,
    const ulonglong2* __restrict__ ts2, int lane, int t0, u64x Vr[4], u64x Vi[4])
{
#pragma unroll 2
    for (int pos = lo; pos < hi; pos++) {
        int2 pf = sperm[pos];
        ulonglong2 A = sAd[pf.x * 32 + lane], B = sBd[pf.x * 32 + lane];
        u64x nAx = neg2(A.x), nAy = neg2(A.y);
        u64x nBx = neg2(B.x), nBy = neg2(B.y);
        int id = (pf.y * t0) & 4095;
#pragma unroll
        for (int j = 0; j < 2; j++) {
            ulonglong2 cs = ts2[id];
            Vr[j * 2 + 0] = fma2(A.x, cs.x, Vr[j * 2 + 0]);  Vr[j * 2 + 0] = fma2(B.x, cs.y, Vr[j * 2 + 0]);
            Vr[j * 2 + 1] = fma2(A.y, cs.x, Vr[j * 2 + 1]);  Vr[j * 2 + 1] = fma2(B.y, cs.y, Vr[j * 2 + 1]);
            if (!FOLD) {
                Vi[j * 2 + 0] = fma2(A.x, cs.y, Vi[j * 2 + 0]);  Vi[j * 2 + 0] = fma2(nBx, cs.x, Vi[j * 2 + 0]);
                Vi[j * 2 + 1] = fma2(A.y, cs.y, Vi[j * 2 + 1]);  Vi[j * 2 + 1] = fma2(nBy, cs.x, Vi[j * 2 + 1]);
            } else {
                Vi[j * 2 + 0] = fma2(B.x, cs.x, Vi[j * 2 + 0]);  Vi[j * 2 + 0] = fma2(nAx, cs.y, Vi[j * 2 + 0]);
                Vi[j * 2 + 1] = fma2(B.y, cs.x, Vi[j * 2 + 1]);  Vi[j * 2 + 1] = fma2(nAy, cs.y, Vi[j * 2 + 1]);
            }
            id = (id + pf.y) & 4095;
        }
    }
}

#define K3_SMEM (4096 * 16 + 32768 + 32768 + 128 * 33 * 4 + 64 * 8 + 64)
__global__ void __launch_bounds__(512, 1) k3_inverse(float* __restrict__ out,
                                                     const int* __restrict__ iq) {
    extern __shared__ char sm[];
    ulonglong2* ts2 = (ulonglong2*)sm;
    float* sA = (float*)(ts2 + 4096);
    float* sB = sA + 64 * 128;
    float* sT = sB + 64 * 128;                    // [128 rows][33]
    int2* sperm = (int2*)(sT + 128 * 33);
    int* soff = (int*)(sperm + 64);

    const int rt = blockIdx.x;
    const int tq = blockIdx.y;
    const int r0 = rt * 128;
    const int tid = threadIdx.x, lane = tid & 31, warp = tid >> 5;

    for (int i = tid; i < 4096; i += 512) ts2[i] = g_ts[i];
    for (int i = tid; i < 8192; i += 512) {
        int rr = i >> 6, f = i & 63;
        float2 v = g_O[(size_t)(r0 + rr) * NM + f];
        int half = rr >> 6, pr = (rr & 63) >> 1, sl = half * 2 + (rr & 1);
        sA[f * 128 + pr * 4 + sl] = v.x;
        sB[f * 128 + pr * 4 + sl] = v.y;
    }
    if (warp == 0) {
        const unsigned FULL = 0xffffffffu;
        int Flo = iq[lane], Fhi = iq[lane + 32];
        int clo = Flo & 7, chi = Fhi & 7;
        unsigned mlo[8], mhi[8];
        int off[9]; off[0] = 0;
#pragma unroll
        for (int c = 0; c < 8; c++) {
            mlo[c] = __ballot_sync(FULL, clo == c);
            mhi[c] = __ballot_sync(FULL, chi == c);
        }
#pragma unroll
        for (int c = 0; c < 8; c++) off[c + 1] = off[c] + __popc(mlo[c]) + __popc(mhi[c]);
        unsigned lmm = (1u << lane) - 1u;
        int p_lo = off[clo] + __popc(mlo[clo] & lmm);
        int p_hi = off[chi] + __popc(mlo[chi]) + __popc(mhi[chi] & lmm);
        sperm[p_lo] = make_int2(lane, Flo);
        sperm[p_hi] = make_int2(lane + 32, Fhi);
        if (lane < 9) soff[lane] = off[lane];
    }
    __syncthreads();

    const ulonglong2* sAd = (const ulonglong2*)sA;
    const ulonglong2* sBd = (const ulonglong2*)sB;
    int o[9];
#pragma unroll
    for (int c = 0; c < 9; c++) o[c] = soff[c];

#pragma unroll 1
    for (int pass = 0; pass < 4; pass++) {
        const int t0 = tq * 128 + pass * 32 + warp * 2;
        u64x P0[4], P4[4], V1r[4], V1i[4], V2r[4], V2i[4], V3r[4], V3i[4];
#pragma unroll
        for (int j = 0; j < 4; j++) {
            P0[j] = 0; P4[j] = 0; V1r[j] = 0; V1i[j] = 0;
            V2r[j] = 0; V2i[j] = 0; V3r[j] = 0; V3i[j] = 0;
        }

        k3_seg_real(o[0], o[1], sperm, sAd, sBd, ts2, lane, t0, P0);
        k3_seg_cplx<false>(o[1], o[2], sperm, sAd, sBd, ts2, lane, t0, V1r, V1i);
        k3_seg_cplx<false>(o[2], o[3], sperm, sAd, sBd, ts2, lane, t0, V2r, V2i);
        k3_seg_cplx<false>(o[3], o[4], sperm, sAd, sBd, ts2, lane, t0, V3r, V3i);
        k3_seg_real(o[4], o[5], sperm, sAd, sBd, ts2, lane, t0, P4);
        k3_seg_cplx<true>(o[5], o[6], sperm, sAd, sBd, ts2, lane, t0, V3r, V3i);
        k3_seg_cplx<true>(o[6], o[7], sperm, sAd, sBd, ts2, lane, t0, V2r, V2i);
        k3_seg_cplx<true>(o[7], o[8], sperm, sAd, sBd, ts2, lane, t0, V1r, V1i);

#pragma unroll 1
        for (int m = 0; m < 8; m++) {
            __syncthreads();
#pragma unroll
            for (int j = 0; j < 2; j++) {
#pragma unroll
                for (int p = 0; p < 2; p++) {
                    const int q = j * 2 + p;
                    u64x a = add2(P0[q], P4[q]);
                    u64x bb = sub2(P0[q], P4[q]);
                    u64x S;
                    if (m == 0) {
                        S = add2(add2(a, V1r[q]), add2(V2r[q], V3r[q]));
                    } else if (m == 1) {
                        u64x t1 = fma2(sub2(V1r[q], V1i[q]), KK2, bb);
                        u64x u2 = fma2(add2(V3r[q], V3i[q]), NKK2, neg2(V2i[q]));
                        S = add2(t1, u2);
                    } else if (m == 2) {
                        S = add2(sub2(sub2(a, V1i[q]), V2r[q]), V3i[q]);
                    } else if (m == 3) {
                        u64x t2 = fma2(add2(V1r[q], V1i[q]), NKK2, bb);
                        u64x u1 = fma2(sub2(V3r[q], V3i[q]), KK2, V2i[q]);
                        S = add2(t2, u1);
                    } else if (m == 4) {
                        S = sub2(add2(sub2(a, V1r[q]), V2r[q]), V3r[q]);   // a - V1r + V2r - V3r
                    } else if (m == 5) {
                        u64x t1 = fma2(sub2(V1r[q], V1i[q]), NKK2, bb);
                        u64x u2 = fma2(add2(V3r[q], V3i[q]), KK2, neg2(V2i[q]));
                        S = add2(t1, u2);
                    } else if (m == 6) {
                        S = sub2(sub2(add2(a, V1i[q]), V2r[q]), V3i[q]);
                    } else {
                        u64x t2 = fma2(add2(V1r[q], V1i[q]), KK2, bb);
                        u64x u1 = fma2(sub2(V3r[q], V3i[q]), NKK2, V2i[q]);
                        S = add2(t2, u1);
                    }
                    float v0, v1;
                    unpack2(S, v0, v1);
                    int tl = warp * 2 + j;
                    int rbase = p * 64 + 2 * lane;
                    sT[rbase * 33 + tl]       = v0;
                    sT[(rbase + 1) * 33 + tl] = v1;
                }
            }
            __syncthreads();
            int tbase = m * 512 + tq * 128 + pass * 32;
#pragma unroll
            for (int ii = 0; ii < 2; ii++) {
                int i = ii * 512 + tid;
                int rr = i >> 3, c4 = i & 7;
                const float* sp = sT + rr * 33 + c4 * 4;
                float4 vv = make_float4(sp[0], sp[1], sp[2], sp[3]);
                *(float4*)&out[(size_t)(r0 + rr) * NL + tbase + c4 * 4] = vv;
            }
        }
    }
}

// ================= launch =================
extern "C" void kernel_launch(void* const* d_in, const int* in_sizes, int n_in,
                              void* d_out, int out_size) {
    const float* q  = (const float*)d_in[0];
    const float* k  = (const float*)d_in[1];
    const float* w1 = (const float*)d_in[3];
    const float* w2 = (const float*)d_in[4];
    const int* iq   = (const int*)d_in[5];
    const int* ikv  = (const int*)d_in[6];
    float* out = (float*)d_out;

    cudaFuncSetAttribute(k1_forward, cudaFuncAttributeMaxDynamicSharedMemorySize, K1_SMEM);
    cudaFuncSetAttribute(k2a_attn,   cudaFuncAttributeMaxDynamicSharedMemorySize, K2A_SMEM);
    cudaFuncSetAttribute(k2b_wproj,  cudaFuncAttributeMaxDynamicSharedMemorySize, K2B_SMEM);
    cudaFuncSetAttribute(k3_inverse, cudaFuncAttributeMaxDynamicSharedMemorySize, K3_SMEM);

    k0_init<<<16, 256>>>();
    k1_forward<<<dim3(4, NB, 8), 256, K1_SMEM>>>(q, k, iq, ikv);
    k2a_attn<<<dim3(NB * NH, 2), 256, K2A_SMEM>>>();
    k2b_wproj<<<dim3(NH, 16), 256, K2B_SMEM>>>(w1, w2, iq);
    k3_inverse<<<dim3(32, 4), 512, K3_SMEM>>>(out, iq);
}